// round 15
// baseline (speedup 1.0000x reference)
#include <cuda_runtime.h>
#include <cuda_fp16.h>
#include <math.h>
#include <stdint.h>

#define NBLK 148

// ---------------- static device scratch ----------------
__device__ __align__(16) float g_XALL[2*512*4096];   // [iou(3072) | f(1024)] per row
__device__ __align__(16) float g_H[2*512*1024];
__device__ __align__(16) float g_C[2*512*1024];
__device__ __align__(16) float g_IOU[2*256*3072];    // two split-K partials
__device__ __align__(16) float g_FP[2*512*1024];     // two split-K partials
__device__ __align__(16) float g_HB[1024*256];
__device__ __align__(16) float g_LOG[1024*16];
__device__ __align__(16) float g_ALPHA[2*16*512];
__device__ __align__(16) float g_Mm[32*1024];
__device__ __align__(16) float g_LSp[4*32*1024];     // wf split-K partials
__device__ __align__(16) float g_FR[3072];
__device__ __align__(16) float g_FC[512];
// half-precision operand copies
__device__ __align__(16) __half g_Wx[4096*1024];     // [w_ioux rows | w_fx rows]
__device__ __align__(16) __half g_Wiouh[3072*1024];
__device__ __align__(16) __half g_Wfh[1024*1024];
__device__ __align__(16) __half g_Ws1h[256*1024];
__device__ __align__(16) __half g_Xh[1024*1024];
__device__ __align__(16) __half g_Hh[2*512*1024];

// ---------------- compile-time tree schedule (N=512 heap, DFS post-order) ----------------
struct Sched {
    int leaf[256];
    int cnt[16];
    int lvl[16][128];
};

constexpr Sched make_sched() {
    Sched s{};
    int order[512] = {}; int rankOf[512] = {}; int height[512] = {};
    int stN[64] = {}; int stP[64] = {};
    int sp = 1, cnt = 0;
    stN[0] = 0; stP[0] = 0;
    while (sp) {
        int j = stN[sp-1], p = stP[sp-1];
        if (p < 2) {
            stP[sp-1] = p + 1;
            int c = 2*j + 1 + p;
            if (c < 512) { stN[sp] = c; stP[sp] = 0; sp++; }
        } else { order[cnt] = j; rankOf[j] = cnt; cnt++; sp--; }
    }
    int nleaf = 0;
    for (int r = 0; r < 512; r++) {
        int j = order[r]; int h = 0;
        for (int k = 0; k < 2; k++) {
            int c = 2*j + 1 + k;
            if (c < 512) { int hh = height[rankOf[c]] + 1; if (hh > h) h = hh; }
        }
        height[r] = h;
        if (h == 0) s.leaf[nleaf++] = r;
        else        s.lvl[h][s.cnt[h]++] = r;
    }
    return s;
}

__device__ const Sched d_S = make_sched();

__device__ __forceinline__ float sigm(float x){ return 1.f/(1.f+expf(-x)); }

__device__ __forceinline__ uint2 f4_to_h4(float4 v){
    __half2 p0 = __floats2half2_rn(v.x, v.y);
    __half2 p1 = __floats2half2_rn(v.z, v.w);
    uint2 r; r.x = *(uint32_t*)&p0; r.y = *(uint32_t*)&p1;
    return r;
}

__device__ __forceinline__ uint32_t smem_u32(const void* p){
    uint32_t a;
    asm("{ .reg .u64 t; cvta.to.shared.u64 t, %1; cvt.u32.u64 %0, t; }" : "=r"(a) : "l"(p));
    return a;
}
__device__ __forceinline__ void cpa16(uint32_t dst, const void* src){
    asm volatile("cp.async.cg.shared.global [%0], [%1], 16;" :: "r"(dst), "l"(src));
}

__device__ __forceinline__ void mma_f16(float c[4],
    uint32_t a0, uint32_t a1, uint32_t a2, uint32_t a3,
    uint32_t b0, uint32_t b1)
{
    asm volatile(
        "mma.sync.aligned.m16n8k16.row.col.f32.f16.f16.f32 "
        "{%0,%1,%2,%3}, {%4,%5,%6,%7}, {%8,%9}, {%0,%1,%2,%3};"
        : "+f"(c[0]), "+f"(c[1]), "+f"(c[2]), "+f"(c[3])
        : "r"(a0), "r"(a1), "r"(a2), "r"(a3), "r"(b0), "r"(b1));
}

// ---------------- grid-wide barrier (all NBLK blocks co-resident: 1 block/SM) ----------------
__device__ unsigned g_barCnt = 0;
__device__ volatile unsigned g_barGen = 0;

__device__ __forceinline__ void grid_bar()
{
    __syncthreads();
    if (threadIdx.x == 0) {
        unsigned gen = g_barGen;
        __threadfence();
        if (atomicAdd(&g_barCnt, 1u) == gridDim.x - 1u) {
            g_barCnt = 0u;
            __threadfence();
            g_barGen = gen + 1u;
        } else {
            while (g_barGen == gen) __nanosleep(64);
        }
    }
    __syncthreads();
}

// ---------------- weight pre-conversion (fp32 -> half), flat ----------------
// cumulative float4 groups: 786432 / 1048576 / 1835008 / 2097152 / 2162688
__global__ void k_cvtW(const float* __restrict__ w_ioux, const float* __restrict__ w_fx,
                       const float* __restrict__ w_iouh, const float* __restrict__ w_fh,
                       const float* __restrict__ ws1)
{
    int i = blockIdx.x*256 + threadIdx.x;
    if (i >= 2162688) return;
    const float4* src; uint2* dst;
    if (i < 786432)       { src = (const float4*)w_ioux + i;            dst = (uint2*)g_Wx + i; }
    else if (i < 1048576) { int j = i -  786432; src = (const float4*)w_fx   + j; dst = (uint2*)g_Wx + 786432 + j; }
    else if (i < 1835008) { int j = i - 1048576; src = (const float4*)w_iouh + j; dst = (uint2*)g_Wiouh + j; }
    else if (i < 2097152) { int j = i - 1835008; src = (const float4*)w_fh   + j; dst = (uint2*)g_Wfh + j; }
    else                  { int j = i - 2097152; src = (const float4*)ws1    + j; dst = (uint2*)g_Ws1h + j; }
    *dst = f4_to_h4(*src);
}

// ---------------- level GEMM tile (fp16, cp.async B, gathered A, k-half 512) ----------------
__device__ void do_lvl_tile(
    int which, int khalf, int rowBase, int colBase, int h, int Bn,
    const int* __restrict__ cidx, const float* __restrict__ cmask,
    uint32_t SA[3][128][20], uint32_t SB[3][64][20])
{
    const int Mrows = which ? 4*Bn : 2*Bn;
    const int Nn    = which ? 1024 : 3072;
    const __half* Bw = which ? g_Wfh : g_Wiouh;
    float* Cout = which ? (g_FP + (size_t)khalf*512*1024)
                        : (g_IOU + (size_t)khalf*256*3072);
    const int kbase = khalf * 512;

    const int tid  = threadIdx.x;
    const int lane = tid & 31, warp = tid >> 5;
    const int wr = warp >> 1, wc = warp & 1;
    const int g  = lane >> 2, tg = lane & 3;
    const uint32_t baB = smem_u32(&SB[0][0][0]);

    const __half* aptr0[2]; const __half* aptr1[2];
    __half2 am0[2], am1[2]; bool avalid[2]; int arow[2], ach[2];
    #pragma unroll
    for (int it = 0; it < 2; it++) {
        int idx = tid + (it << 8);
        int row = idx >> 2, ch = idx & 3;
        arow[it] = row; ach[it] = ch;
        int gr = rowBase + row;
        avalid[it] = (gr < Mrows);
        if (avalid[it]) {
            if (which == 0) {
                int t = gr >= Bn; int j = gr - (t ? Bn : 0);
                int r = d_S.lvl[h][j];
                aptr0[it] = g_Hh + ((size_t)(t*512 + cidx[2*r  ]))*1024 + ch*8;
                aptr1[it] = g_Hh + ((size_t)(t*512 + cidx[2*r+1]))*1024 + ch*8;
                am0[it] = __float2half2_rn(cmask[2*r]);
                am1[it] = __float2half2_rn(cmask[2*r+1]);
            } else {
                int t = gr >= 2*Bn; int rem = gr - (t ? 2*Bn : 0);
                int j = rem >> 1, ck = rem & 1;
                int r = d_S.lvl[h][j];
                aptr0[it] = g_Hh + ((size_t)(t*512 + cidx[2*r+ck]))*1024 + ch*8;
                aptr1[it] = aptr0[it];
                am0[it] = __float2half2_rn(cmask[2*r+ck]);
                am1[it] = __float2half2_rn(0.f);
            }
        }
    }

    {   // zero-fill invalid A rows in all stages
        const uint4 zz = make_uint4(0,0,0,0);
        #pragma unroll
        for (int s = 0; s < 3; s++)
            #pragma unroll
            for (int it = 0; it < 2; it++)
                if (!avalid[it]) *(uint4*)&SA[s][arow[it]][ach[it]*4] = zz;
    }

    auto issueB = [&](int stage, int k0){
        int row = tid >> 2, ch = tid & 3;
        cpa16(baB + ((stage*64 + row)*20 + ch*4)*4,
              Bw + (size_t)(colBase + row)*1024 + k0 + ch*8);
        asm volatile("cp.async.commit_group;" ::: "memory");
    };

    float acc[2][4][4];
    #pragma unroll
    for (int i=0;i<2;i++) for (int j=0;j<4;j++) for (int e=0;e<4;e++) acc[i][j][e]=0.f;

    uint4 va[2];
    auto gatherA = [&](int k0){
        #pragma unroll
        for (int it = 0; it < 2; it++) {
            if (!avalid[it]) continue;
            uint4 u0 = *(const uint4*)(aptr0[it] + k0);
            uint4 u1 = *(const uint4*)(aptr1[it] + k0);
            __half2* a = (__half2*)&u0; __half2* b = (__half2*)&u1;
            uint4 r; __half2* o = (__half2*)&r;
            #pragma unroll
            for (int w = 0; w < 4; w++)
                o[w] = (which==0) ? __hfma2(b[w], am1[it], __hmul2(a[w], am0[it]))
                                  : __hmul2(a[w], am0[it]);
            va[it] = r;
        }
    };
    auto stsA = [&](int stage){
        #pragma unroll
        for (int it = 0; it < 2; it++)
            if (avalid[it]) *(uint4*)&SA[stage][arow[it]][ach[it]*4] = va[it];
    };

    gatherA(kbase);      stsA(0); issueB(0, kbase);
    gatherA(kbase + 32); stsA(1); issueB(1, kbase + 32);

    for (int c = 0; c < 16; c++) {
        const int stage = c % 3;
        const int kn = (c + 2) * 32;
        const int nst = (c + 2) % 3;
        if (kn < 512) gatherA(kbase + kn);
        if (kn < 512) { asm volatile("cp.async.wait_group 1;" ::: "memory"); }
        else          { asm volatile("cp.async.wait_group 0;" ::: "memory"); }
        __syncthreads();
        if (kn < 512) { stsA(nst); issueB(nst, kbase + kn); }
        #pragma unroll
        for (int s = 0; s < 2; s++) {
            const int kp = s*8;
            uint32_t a[2][4];
            #pragma unroll
            for (int i = 0; i < 2; i++) {
                int mb = wr*32 + i*16 + g;
                a[i][0] = SA[stage][mb    ][kp + tg];
                a[i][1] = SA[stage][mb + 8][kp + tg];
                a[i][2] = SA[stage][mb    ][kp + 4 + tg];
                a[i][3] = SA[stage][mb + 8][kp + 4 + tg];
            }
            uint32_t b[4][2];
            #pragma unroll
            for (int j = 0; j < 4; j++) {
                int nb = wc*32 + j*8 + g;
                b[j][0] = SB[stage][nb][kp + tg];
                b[j][1] = SB[stage][nb][kp + 4 + tg];
            }
            #pragma unroll
            for (int i = 0; i < 2; i++)
                #pragma unroll
                for (int j = 0; j < 4; j++)
                    mma_f16(acc[i][j], a[i][0], a[i][1], a[i][2], a[i][3],
                            b[j][0], b[j][1]);
        }
        __syncthreads();
    }

    #pragma unroll
    for (int i = 0; i < 2; i++)
        #pragma unroll
        for (int j = 0; j < 4; j++) {
            int r0 = rowBase + wr*32 + i*16 + g;
            int c0 = colBase + wc*32 + j*8 + tg*2;
            #pragma unroll
            for (int e = 0; e < 4; e++) {
                int row = r0 + ((e >> 1) ? 8 : 0);
                int col = c0 + (e & 1);
                if (row < Mrows)
                    Cout[(size_t)row*Nn + col] = acc[i][j][e];
            }
        }
}

// ---------------- persistent tree kernel: leaves + 9 levels, grid barriers ----------------
__global__ __launch_bounds__(256)
void k_tree(const int* __restrict__ cidx, const float* __restrict__ cmask,
            const float* __restrict__ b_iouh, const float* __restrict__ b_fh)
{
    __shared__ uint32_t SA[3][128][20];
    __shared__ uint32_t SB[3][64][20];
    const int bid = blockIdx.x, tid = threadIdx.x;
    const int NB = gridDim.x;

    // ---- leaves ----
    for (int gid = bid*256 + tid; gid < 2*256*1024; gid += NB*256) {
        int i = gid >> 10, m = gid & 1023;
        int t = i >> 8, j = i & 255;
        int r = d_S.leaf[j];
        size_t x = (size_t)(t*512 + r);
        float ig = g_XALL[x*4096 + m]        + b_iouh[m];
        float og = g_XALL[x*4096 + 1024 + m] + b_iouh[1024 + m];
        float ug = g_XALL[x*4096 + 2048 + m] + b_iouh[2048 + m];
        float c = sigm(ig) * tanhf(ug);
        float hv = sigm(og) * tanhf(c);
        g_C[x*1024 + m] = c;
        g_H[x*1024 + m] = hv;
        g_Hh[x*1024 + m] = __float2half(hv);
    }
    grid_bar();

    // ---- internal levels ----
    for (int h = 1; h <= 15; h++) {
        int B = d_S.cnt[h];
        if (B == 0) continue;
        int my0 = (2*B + 127) >> 7;
        int my1 = (4*B + 127) >> 7;
        int T0 = 48*my0*2;
        int T  = T0 + 16*my1*2;
        for (int t = bid; t < T; t += NB) {
            int which, khalf, myi, col;
            if (t < T0) { which = 0; int r = t;      khalf = r & 1; r >>= 1; col = r % 48; myi = r / 48; }
            else        { which = 1; int r = t - T0; khalf = r & 1; r >>= 1; col = r & 15; myi = r >> 4; }
            do_lvl_tile(which, khalf, myi*128, col*64, h, B, cidx, cmask, SA, SB);
        }
        grid_bar();

        const size_t IOFF = (size_t)256*3072;
        const size_t FOFF = (size_t)512*1024;
        for (int gid = bid*256 + tid; gid < 2*B*1024; gid += NB*256) {
            int i = gid >> 10, m = gid & 1023;
            int t = i >= B; int j = i - (t ? B : 0);
            int r = d_S.lvl[h][j];
            size_t x = (size_t)(t*512 + r);
            // g_IOU/g_FP rows are REUSED across levels within this launch -> bypass L1
            float iou0 = __ldcg(&g_IOU[(size_t)i*3072 + m])        + __ldcg(&g_IOU[IOFF + (size_t)i*3072 + m]);
            float iou1 = __ldcg(&g_IOU[(size_t)i*3072 + 1024 + m]) + __ldcg(&g_IOU[IOFF + (size_t)i*3072 + 1024 + m]);
            float iou2 = __ldcg(&g_IOU[(size_t)i*3072 + 2048 + m]) + __ldcg(&g_IOU[IOFF + (size_t)i*3072 + 2048 + m]);
            float ig = g_XALL[x*4096 + m]        + iou0 + b_iouh[m];
            float og = g_XALL[x*4096 + 1024 + m] + iou1 + b_iouh[1024 + m];
            float ug = g_XALL[x*4096 + 2048 + m] + iou2 + b_iouh[2048 + m];
            float xf = g_XALL[x*4096 + 3072 + m];
            float fp0 = __ldcg(&g_FP[(size_t)(2*i  )*1024 + m]) + __ldcg(&g_FP[FOFF + (size_t)(2*i  )*1024 + m]);
            float fp1 = __ldcg(&g_FP[(size_t)(2*i+1)*1024 + m]) + __ldcg(&g_FP[FOFF + (size_t)(2*i+1)*1024 + m]);
            float f0 = sigm(fp0 + b_fh[m] + xf);
            float f1 = sigm(fp1 + b_fh[m] + xf);
            int c0 = cidx[2*r], c1 = cidx[2*r+1];
            float m0 = cmask[2*r], m1 = cmask[2*r+1];
            float cc0 = g_C[((size_t)(t*512 + c0))*1024 + m] * m0;
            float cc1 = g_C[((size_t)(t*512 + c1))*1024 + m] * m1;
            float c = sigm(ig)*tanhf(ug) + f0*cc0 + f1*cc1;
            float hv = sigm(og)*tanhf(c);
            g_C[x*1024 + m] = c;
            g_H[x*1024 + m] = hv;
            g_Hh[x*1024 + m] = __float2half(hv);
        }
        grid_bar();
    }
}

// ---------------- fp16 cp.async-pipelined GEMM (dense A), 128x64 tile ----
// MODE 0: A = g_Xh (M=1024), B = g_Wx (N=4096), C = g_XALL + split bias
// MODE 2: A = g_Hh (M=1024), B = g_Ws1h (N=256), C = tanh -> g_HB
template<int MODE>
__global__ __launch_bounds__(256)
void gemm_h(const float* __restrict__ b1, const float* __restrict__ b2)
{
    const __half* Aw = (MODE == 0) ? g_Xh : g_Hh;
    const __half* Bw = (MODE == 0) ? g_Wx : g_Ws1h;
    const int Nn = (MODE == 0) ? 4096 : 256;
    const int rowBase = blockIdx.y * 128;
    const int colBase = blockIdx.x * 64;

    __shared__ uint32_t SA[3][128][20];
    __shared__ uint32_t SB[3][64][20];

    const int tid  = threadIdx.x;
    const int lane = tid & 31, warp = tid >> 5;
    const int wr = warp >> 1, wc = warp & 1;
    const int g  = lane >> 2, tg = lane & 3;

    const uint32_t baA = smem_u32(&SA[0][0][0]);
    const uint32_t baB = smem_u32(&SB[0][0][0]);

    auto issue = [&](int stage, int k0){
        {
            int row = tid >> 2, ch = tid & 3;
            cpa16(baB + ((stage*64 + row)*20 + ch*4)*4,
                  Bw + (size_t)(colBase + row)*1024 + k0 + ch*8);
        }
        #pragma unroll
        for (int it = 0; it < 2; it++) {
            int idx = tid + (it << 8);
            int row = idx >> 2, ch = idx & 3;
            cpa16(baA + ((stage*128 + row)*20 + ch*4)*4,
                  Aw + (size_t)(rowBase + row)*1024 + k0 + ch*8);
        }
        asm volatile("cp.async.commit_group;" ::: "memory");
    };

    float acc[2][4][4];
    #pragma unroll
    for (int i=0;i<2;i++) for (int j=0;j<4;j++) for (int e=0;e<4;e++) acc[i][j][e]=0.f;

    issue(0, 0);
    issue(1, 32);

    for (int c = 0; c < 32; c++) {
        const int stage = c % 3;
        const int kn = (c + 2) * 32;
        const int nst = (c + 2) % 3;
        if (kn < 1024) { asm volatile("cp.async.wait_group 1;" ::: "memory"); }
        else           { asm volatile("cp.async.wait_group 0;" ::: "memory"); }
        __syncthreads();
        if (kn < 1024) issue(nst, kn);
        #pragma unroll
        for (int s = 0; s < 2; s++) {
            const int kp = s*8;
            uint32_t a[2][4];
            #pragma unroll
            for (int i = 0; i < 2; i++) {
                int mb = wr*32 + i*16 + g;
                a[i][0] = SA[stage][mb    ][kp + tg];
                a[i][1] = SA[stage][mb + 8][kp + tg];
                a[i][2] = SA[stage][mb    ][kp + 4 + tg];
                a[i][3] = SA[stage][mb + 8][kp + 4 + tg];
            }
            uint32_t b[4][2];
            #pragma unroll
            for (int j = 0; j < 4; j++) {
                int nb = wc*32 + j*8 + g;
                b[j][0] = SB[stage][nb][kp + tg];
                b[j][1] = SB[stage][nb][kp + 4 + tg];
            }
            #pragma unroll
            for (int i = 0; i < 2; i++)
                #pragma unroll
                for (int j = 0; j < 4; j++)
                    mma_f16(acc[i][j], a[i][0], a[i][1], a[i][2], a[i][3],
                            b[j][0], b[j][1]);
        }
        __syncthreads();
    }

    #pragma unroll
    for (int i = 0; i < 2; i++)
        #pragma unroll
        for (int j = 0; j < 4; j++) {
            int r0 = rowBase + wr*32 + i*16 + g;
            int c0 = colBase + wc*32 + j*8 + tg*2;
            #pragma unroll
            for (int e = 0; e < 4; e++) {
                int row = r0 + ((e >> 1) ? 8 : 0);
                int col = c0 + (e & 1);
                if (MODE == 0) {
                    float bias = (col < 3072) ? b1[col] : b2[col-3072];
                    g_XALL[(size_t)row*4096 + col] = acc[i][j][e] + bias;
                } else {
                    g_HB[(size_t)row*256 + col] = tanhf(acc[i][j][e]);
                }
            }
        }
}

// ---------------- tf32 small GEMM (ldA/ldB explicit; batched/split-K via z strides) ----
__device__ __forceinline__ uint32_t f2tf32(float x){
    uint32_t r;
    asm("cvt.rna.tf32.f32 %0, %1;" : "=r"(r) : "f"(x));
    return r;
}
__device__ __forceinline__ void mma_tf32(float c[4],
    uint32_t a0, uint32_t a1, uint32_t a2, uint32_t a3,
    uint32_t b0, uint32_t b1)
{
    asm volatile(
        "mma.sync.aligned.m16n8k8.row.col.f32.tf32.tf32.f32 "
        "{%0,%1,%2,%3}, {%4,%5,%6,%7}, {%8,%9}, {%0,%1,%2,%3};"
        : "+f"(c[0]), "+f"(c[1]), "+f"(c[2]), "+f"(c[3])
        : "r"(a0), "r"(a1), "r"(a2), "r"(a3), "r"(b0), "r"(b1));
}
__device__ __forceinline__ void sts_row(uint32_t S[][20], int row, int k4, float4 v){
    uint4 t;
    t.x = f2tf32(v.x); t.y = f2tf32(v.y);
    t.z = f2tf32(v.z); t.w = f2tf32(v.w);
    *(uint4*)&S[row][k4] = t;
}
__device__ __forceinline__ void mma_tile16(float acc[2][4][4],
        const uint32_t As[][20], const uint32_t Bs[][20],
        int wr, int wc, int g, int tg)
{
    #pragma unroll
    for (int ks = 0; ks < 16; ks += 8) {
        uint32_t a[2][4];
        #pragma unroll
        for (int i = 0; i < 2; i++) {
            int mb = wr*32 + i*16 + g;
            a[i][0] = As[mb    ][ks + tg];
            a[i][1] = As[mb + 8][ks + tg];
            a[i][2] = As[mb    ][ks + 4 + tg];
            a[i][3] = As[mb + 8][ks + 4 + tg];
        }
        uint32_t b[4][2];
        #pragma unroll
        for (int j = 0; j < 4; j++) {
            int nb = wc*32 + j*8 + g;
            b[j][0] = Bs[nb][ks + tg];
            b[j][1] = Bs[nb][ks + 4 + tg];
        }
        #pragma unroll
        for (int i = 0; i < 2; i++)
            #pragma unroll
            for (int j = 0; j < 4; j++)
                mma_tf32(acc[i][j], a[i][0], a[i][1], a[i][2], a[i][3],
                         b[j][0], b[j][1]);
    }
}

template<bool BT, int ACT>
__global__ __launch_bounds__(128) void gemm_s(
    const float* __restrict__ A, const float* __restrict__ B,
    const float* __restrict__ bias, float* __restrict__ C,
    int M, int N, int K, int ldA, int ldB,
    int sA, int sB, int sC)
{
    A += (size_t)blockIdx.z * sA;
    B += (size_t)blockIdx.z * sB;
    C += (size_t)blockIdx.z * sC;

    __shared__ uint32_t As[2][64][20];
    __shared__ uint32_t Bs[2][64][20];
    const int tid  = threadIdx.x;
    const int lane = tid & 31, warp = tid >> 5;
    const int wr = warp >> 1, wc = warp & 1;
    const int g = lane >> 2, tg = lane & 3;
    const int rowBase = blockIdx.y*64, colBase = blockIdx.x*64;

    float4 rA[2], rB[2];
    auto loadA = [&](int k0){
        #pragma unroll
        for (int it = 0; it < 2; it++) {
            int idx = tid + it*128, row = idx >> 2, k4 = (idx & 3)*4;
            int gr = rowBase + row;
            rA[it] = (gr < M) ? *(const float4*)(A + (size_t)gr*ldA + k0 + k4)
                              : make_float4(0.f,0.f,0.f,0.f);
        }
    };
    auto loadB = [&](int k0){
        #pragma unroll
        for (int it = 0; it < 2; it++) {
            int idx = tid + it*128;
            if (BT) {
                int row = idx >> 2, k4 = (idx & 3)*4;
                int gn = colBase + row;
                rB[it] = (gn < N) ? *(const float4*)(B + (size_t)gn*ldB + k0 + k4)
                                  : make_float4(0.f,0.f,0.f,0.f);
            } else {
                int k = idx >> 4, n4 = (idx & 15)*4;
                rB[it] = *(const float4*)(B + (size_t)(k0+k)*ldB + colBase + n4);
            }
        }
    };
    auto stsAll = [&](int buf){
        #pragma unroll
        for (int it = 0; it < 2; it++) {
            int idx = tid + it*128;
            int rowA = idx >> 2, k4 = (idx & 3)*4;
            sts_row(As[buf], rowA, k4, rA[it]);
            if (BT) {
                sts_row(Bs[buf], rowA, k4, rB[it]);
            } else {
                int k = idx >> 4, n4 = (idx & 15)*4;
                Bs[buf][n4+0][k] = f2tf32(rB[it].x);
                Bs[buf][n4+1][k] = f2tf32(rB[it].y);
                Bs[buf][n4+2][k] = f2tf32(rB[it].z);
                Bs[buf][n4+3][k] = f2tf32(rB[it].w);
            }
        }
    };

    float acc[2][4][4];
    #pragma unroll
    for (int i=0;i<2;i++) for (int j=0;j<4;j++) for (int e=0;e<4;e++) acc[i][j][e]=0.f;

    loadA(0); loadB(0); stsAll(0); __syncthreads();
    int buf = 0;
    for (int k0 = 16; ; k0 += 16) {
        bool more = (k0 < K);
        if (more) { loadA(k0); loadB(k0); }
        mma_tile16(acc, As[buf], Bs[buf], wr, wc, g, tg);
        if (!more) break;
        buf ^= 1;
        stsAll(buf);
        __syncthreads();
    }

    #pragma unroll
    for (int i = 0; i < 2; i++)
        #pragma unroll
        for (int j = 0; j < 4; j++) {
            int r0 = rowBase + wr*32 + i*16 + g;
            int c0 = colBase + wc*32 + j*8 + tg*2;
            #pragma unroll
            for (int e = 0; e < 4; e++) {
                int row = r0 + ((e >> 1) ? 8 : 0);
                int col = c0 + (e & 1);
                if (row < M && col < N) {
                    float v = acc[i][j][e];
                    if (bias) v += bias[col];
                    if (ACT == 1) v = tanhf(v);
                    else if (ACT == 2) v = fmaxf(v, 0.f);
                    C[(size_t)row*N + col] = v;
                }
            }
        }
}

// ---------------- pointwise kernels ----------------
__global__ void k_embed(const int* __restrict__ lin, const int* __restrict__ rin,
                        const float* __restrict__ emb)
{
    int row = blockIdx.x;
    int t = row >> 9, n = row & 511;
    int tok = t ? rin[n] : lin[n];
    float4 v = ((const float4*)(emb + (size_t)tok*1024))[threadIdx.x];
    ((uint2*)(g_Xh + (size_t)row*1024))[threadIdx.x] = f4_to_h4(v);
}

__global__ void k_soft(float* __restrict__ out)
{
    __shared__ float sh[512];
    int b = blockIdx.x;                 // t*16 + hop
    int t = b >> 4, hop = b & 15;
    int n = threadIdx.x;
    float v = g_LOG[(size_t)(t*512 + n)*16 + hop];
    sh[n] = v; __syncthreads();
    for (int s=256; s>0; s>>=1){ if (n < s) sh[n] = fmaxf(sh[n], sh[n+s]); __syncthreads(); }
    float mx = sh[0]; __syncthreads();
    float e = expf(v - mx);
    sh[n] = e; __syncthreads();
    for (int s=256; s>0; s>>=1){ if (n < s) sh[n] += sh[n+s]; __syncthreads(); }
    float a = e / sh[0];
    g_ALPHA[(size_t)b*512 + n] = a;
    out[5 + t*8192 + hop*512 + n] = a;
}

__global__ void k_lat(const float* __restrict__ w_lat, const float* __restrict__ b_lat)
{
    int m = blockIdx.x*256 + threadIdx.x;   // 1024
    float lv = b_lat[0], rv = b_lat[0];
    #pragma unroll
    for (int h=0; h<16; h++) {
        float w = w_lat[h];
        float sl = 0.f, sr = 0.f;
        #pragma unroll
        for (int z=0; z<4; z++) {
            sl += g_LSp[z*32768 + h*1024 + m];
            sr += g_LSp[z*32768 + (16 + h)*1024 + m];
        }
        lv += w * fmaxf(sl, 0.f);
        rv += w * fmaxf(sr, 0.f);
    }
    g_FR[m]        = fabsf(lv - rv);
    g_FR[1024 + m] = lv * rv;
    g_FR[2048 + m] = 0.5f * (lv + rv);
}

__global__ void k_fc(const float* __restrict__ w, const float* __restrict__ bb)
{
    int o = blockIdx.x*8 + (threadIdx.x >> 5);
    int lane = threadIdx.x & 31;
    const float* wr = w + (size_t)o*3072;
    float s = 0.f;
    for (int k=lane; k<3072; k+=32) s += g_FR[k]*wr[k];
    for (int d=16; d; d>>=1) s += __shfl_down_sync(0xffffffffu, s, d);
    if (!lane) { float v = s + bb[o]; g_FC[o] = v > 0.f ? v : 0.01f*v; }
}

__global__ void k_fc2out(const float* __restrict__ w_out, const float* __restrict__ b_out,
                         const float* __restrict__ w_out1, const float* __restrict__ b_out1,
                         float* __restrict__ out)
{
    __shared__ float fc2[256];
    __shared__ float logit[5];
    int tid = threadIdx.x;             // 256
    int wid = tid >> 5, lane = tid & 31;
    for (int it = 0; it < 4; it++) {
        int o = wid*32 + (it << 3) + (lane >> 2);
        float s = 0.f;
        for (int k = (lane & 3); k < 512; k += 4) s += g_FC[k]*w_out[(size_t)o*512 + k];
        s += __shfl_down_sync(0xffffffffu, s, 2);
        s += __shfl_down_sync(0xffffffffu, s, 1);
        if ((lane & 3) == 0) fc2[o] = sigm(s + b_out[o]);
    }
    __syncthreads();
    if (wid < 5) {
        float s = 0.f;
        for (int k = lane; k < 256; k += 32) s += fc2[k]*w_out1[wid*256 + k];
        for (int d = 16; d; d >>= 1) s += __shfl_down_sync(0xffffffffu, s, d);
        if (!lane) logit[wid] = s + b_out1[wid];
    }
    __syncthreads();
    if (tid == 0) {
        float mx = logit[0];
        for (int c=1;c<5;c++) mx = fmaxf(mx, logit[c]);
        float sum = 0.f;
        for (int c=0;c<5;c++) sum += expf(logit[c]-mx);
        float l = logf(sum);
        for (int c=0;c<5;c++) out[c] = logit[c] - mx - l;
    }
}

// ---------------- launch ----------------
extern "C" void kernel_launch(void* const* d_in, const int* in_sizes, int n_in,
                              void* d_out, int out_size)
{
    const int*   linputs    = (const int*)  d_in[0];
    const int*   rinputs    = (const int*)  d_in[1];
    const int*   child_idx  = (const int*)  d_in[2];
    const float* child_mask = (const float*)d_in[3];
    const float* emb        = (const float*)d_in[4];
    const float* w_ioux     = (const float*)d_in[5];
    const float* b_ioux     = (const float*)d_in[6];
    const float* w_iouh     = (const float*)d_in[7];
    const float* b_iouh     = (const float*)d_in[8];
    const float* w_fx       = (const float*)d_in[9];
    const float* b_fx       = (const float*)d_in[10];
    const float* w_fh       = (const float*)d_in[11];
    const float* b_fh       = (const float*)d_in[12];
    const float* ws1        = (const float*)d_in[13];
    const float* ws2        = (const float*)d_in[14];
    const float* wf         = (const float*)d_in[15];
    const float* w_lat      = (const float*)d_in[16];
    const float* b_lat      = (const float*)d_in[17];
    const float* w_fc       = (const float*)d_in[18];
    const float* b_fc       = (const float*)d_in[19];
    const float* w_out      = (const float*)d_in[20];
    const float* b_out      = (const float*)d_in[21];
    const float* w_out1     = (const float*)d_in[22];
    const float* b_out1     = (const float*)d_in[23];
    float* out = (float*)d_out;

    float *pH, *pHB, *pLOG, *pALPHA, *pM, *pLSp;
    cudaGetSymbolAddress((void**)&pH,     g_H);
    cudaGetSymbolAddress((void**)&pHB,    g_HB);
    cudaGetSymbolAddress((void**)&pLOG,   g_LOG);
    cudaGetSymbolAddress((void**)&pALPHA, g_ALPHA);
    cudaGetSymbolAddress((void**)&pM,     g_Mm);
    cudaGetSymbolAddress((void**)&pLSp,   g_LSp);

    // 0) weight conversion to half
    k_cvtW<<<8448, 256>>>(w_ioux, w_fx, w_iouh, w_fh, ws1);

    // 1) embedding gather (half)
    k_embed<<<1024, 256>>>(linputs, rinputs, emb);

    // 2) fused input projections: M=1024, N=4096, K=1024
    gemm_h<0><<<dim3(64, 8, 1), 256>>>(b_ioux, b_fx);

    // 3) persistent kernel: leaves + all internal levels (grid barriers)
    k_tree<<<NBLK, 256>>>(child_idx, child_mask, b_iouh, b_fh);

    // 4) attention
    gemm_h<2><<<dim3(4, 8, 1), 256>>>(nullptr, nullptr);
    gemm_s<true,0><<<dim3(1,16,1), 128>>>(pHB, ws2, nullptr, pLOG,
                                          1024, 16, 256, 256, 256, 0, 0, 0);
    k_soft<<<32, 512>>>(out);
    gemm_s<false,0><<<dim3(16,1,2), 128>>>(pALPHA, pH, nullptr, pM,
                                           16, 1024, 512, 512, 1024,
                                           16*512, 512*1024, 16*1024);

    // 5) head: wf GEMM split-K=4 (K slabs of 256), relu folded into k_lat
    gemm_s<false,0><<<dim3(16,1,4), 128>>>(pM, wf, nullptr, pLSp,
                                           32, 1024, 256, 1024, 1024,
                                           256, 256*1024, 32*1024);
    k_lat<<<4, 256>>>(w_lat, b_lat);
    k_fc<<<64, 256>>>(w_fc, b_fc);
    k_fc2out<<<1, 256>>>(w_out, b_out, w_out1, b_out1, out);
}

// round 16
// speedup vs baseline: 1.0848x; 1.0848x over previous
#include <cuda_runtime.h>
#include <cuda_fp16.h>
#include <math.h>
#include <stdint.h>

// ---------------- static device scratch ----------------
__device__ __align__(16) float g_XALL[2*512*4096];   // [iou(3072) | f(1024)] per row
__device__ __align__(16) float g_H[2*512*1024];
__device__ __align__(16) float g_C[2*512*1024];
__device__ __align__(16) float g_IOU[2*256*3072];    // two split-K partials
__device__ __align__(16) float g_FP[2*512*1024];     // two split-K partials
__device__ __align__(16) float g_HB[1024*256];
__device__ __align__(16) float g_LOG[1024*16];
__device__ __align__(16) float g_ALPHA[2*16*512];
__device__ __align__(16) float g_Mm[32*1024];
__device__ __align__(16) float g_LSp[4*32*1024];     // wf split-K partials
__device__ __align__(16) float g_FR[3072];
__device__ __align__(16) float g_FC[512];
// half-precision operand copies
__device__ __align__(16) __half g_Wx[4096*1024];     // [w_ioux rows | w_fx rows]
__device__ __align__(16) __half g_Wiouh[3072*1024];
__device__ __align__(16) __half g_Wfh[1024*1024];
__device__ __align__(16) __half g_Ws1h[256*1024];
__device__ __align__(16) __half g_Xh[1024*1024];
__device__ __align__(16) __half g_Hh[2*512*1024];

// ---------------- compile-time tree schedule (N=512 heap, DFS post-order) ----------------
struct Sched {
    int leaf[256];
    int cnt[16];
    int lvl[16][128];
};

constexpr Sched make_sched() {
    Sched s{};
    int order[512] = {}; int rankOf[512] = {}; int height[512] = {};
    int stN[64] = {}; int stP[64] = {};
    int sp = 1, cnt = 0;
    stN[0] = 0; stP[0] = 0;
    while (sp) {
        int j = stN[sp-1], p = stP[sp-1];
        if (p < 2) {
            stP[sp-1] = p + 1;
            int c = 2*j + 1 + p;
            if (c < 512) { stN[sp] = c; stP[sp] = 0; sp++; }
        } else { order[cnt] = j; rankOf[j] = cnt; cnt++; sp--; }
    }
    int nleaf = 0;
    for (int r = 0; r < 512; r++) {
        int j = order[r]; int h = 0;
        for (int k = 0; k < 2; k++) {
            int c = 2*j + 1 + k;
            if (c < 512) { int hh = height[rankOf[c]] + 1; if (hh > h) h = hh; }
        }
        height[r] = h;
        if (h == 0) s.leaf[nleaf++] = r;
        else        s.lvl[h][s.cnt[h]++] = r;
    }
    return s;
}

__device__ const Sched d_S = make_sched();

__device__ __forceinline__ float sigm(float x){ return 1.f/(1.f+expf(-x)); }

__device__ __forceinline__ uint2 f4_to_h4(float4 v){
    __half2 p0 = __floats2half2_rn(v.x, v.y);
    __half2 p1 = __floats2half2_rn(v.z, v.w);
    uint2 r; r.x = *(uint32_t*)&p0; r.y = *(uint32_t*)&p1;
    return r;
}

__device__ __forceinline__ uint32_t smem_u32(const void* p){
    uint32_t a;
    asm("{ .reg .u64 t; cvta.to.shared.u64 t, %1; cvt.u32.u64 %0, t; }" : "=r"(a) : "l"(p));
    return a;
}
__device__ __forceinline__ void cpa16(uint32_t dst, const void* src){
    asm volatile("cp.async.cg.shared.global [%0], [%1], 16;" :: "r"(dst), "l"(src));
}

__device__ __forceinline__ void mma_f16(float c[4],
    uint32_t a0, uint32_t a1, uint32_t a2, uint32_t a3,
    uint32_t b0, uint32_t b1)
{
    asm volatile(
        "mma.sync.aligned.m16n8k16.row.col.f32.f16.f16.f32 "
        "{%0,%1,%2,%3}, {%4,%5,%6,%7}, {%8,%9}, {%0,%1,%2,%3};"
        : "+f"(c[0]), "+f"(c[1]), "+f"(c[2]), "+f"(c[3])
        : "r"(a0), "r"(a1), "r"(a2), "r"(a3), "r"(b0), "r"(b1));
}

// ---------------- grid-wide barrier (grid sized for guaranteed co-residency) ----------------
__device__ unsigned g_barCnt = 0;
__device__ volatile unsigned g_barGen = 0;

__device__ __forceinline__ void grid_bar()
{
    __syncthreads();
    if (threadIdx.x == 0) {
        unsigned gen = g_barGen;
        __threadfence();
        if (atomicAdd(&g_barCnt, 1u) == gridDim.x - 1u) {
            g_barCnt = 0u;
            __threadfence();
            g_barGen = gen + 1u;
        } else {
            while (g_barGen == gen) __nanosleep(64);
        }
    }
    __syncthreads();
}

// ---------------- weight pre-conversion (fp32 -> half), flat ----------------
// cumulative float4 groups: 786432 / 1048576 / 1835008 / 2097152 / 2162688
__global__ void k_cvtW(const float* __restrict__ w_ioux, const float* __restrict__ w_fx,
                       const float* __restrict__ w_iouh, const float* __restrict__ w_fh,
                       const float* __restrict__ ws1)
{
    int i = blockIdx.x*256 + threadIdx.x;
    if (i >= 2162688) return;
    const float4* src; uint2* dst;
    if (i < 786432)       { src = (const float4*)w_ioux + i;            dst = (uint2*)g_Wx + i; }
    else if (i < 1048576) { int j = i -  786432; src = (const float4*)w_fx   + j; dst = (uint2*)g_Wx + 786432 + j; }
    else if (i < 1835008) { int j = i - 1048576; src = (const float4*)w_iouh + j; dst = (uint2*)g_Wiouh + j; }
    else if (i < 2097152) { int j = i - 1835008; src = (const float4*)w_fh   + j; dst = (uint2*)g_Wfh + j; }
    else                  { int j = i - 2097152; src = (const float4*)ws1    + j; dst = (uint2*)g_Ws1h + j; }
    *dst = f4_to_h4(*src);
}

// ---------------- level GEMM tile (fp16, cp.async B, gathered A, k-half 512) ----------------
__device__ void do_lvl_tile(
    int which, int khalf, int rowBase, int colBase, int h, int Bn,
    const int* __restrict__ cidx, const float* __restrict__ cmask,
    uint32_t SA[3][128][20], uint32_t SB[3][64][20])
{
    const int Mrows = which ? 4*Bn : 2*Bn;
    const int Nn    = which ? 1024 : 3072;
    const __half* Bw = which ? g_Wfh : g_Wiouh;
    float* Cout = which ? (g_FP + (size_t)khalf*512*1024)
                        : (g_IOU + (size_t)khalf*256*3072);
    const int kbase = khalf * 512;

    const int tid  = threadIdx.x;
    const int lane = tid & 31, warp = tid >> 5;
    const int wr = warp >> 1, wc = warp & 1;
    const int g  = lane >> 2, tg = lane & 3;
    const uint32_t baB = smem_u32(&SB[0][0][0]);

    const __half* aptr0[2]; const __half* aptr1[2];
    __half2 am0[2], am1[2]; bool avalid[2]; int arow[2], ach[2];
    #pragma unroll
    for (int it = 0; it < 2; it++) {
        int idx = tid + (it << 8);
        int row = idx >> 2, ch = idx & 3;
        arow[it] = row; ach[it] = ch;
        int gr = rowBase + row;
        avalid[it] = (gr < Mrows);
        if (avalid[it]) {
            if (which == 0) {
                int t = gr >= Bn; int j = gr - (t ? Bn : 0);
                int r = d_S.lvl[h][j];
                aptr0[it] = g_Hh + ((size_t)(t*512 + cidx[2*r  ]))*1024 + ch*8;
                aptr1[it] = g_Hh + ((size_t)(t*512 + cidx[2*r+1]))*1024 + ch*8;
                am0[it] = __float2half2_rn(cmask[2*r]);
                am1[it] = __float2half2_rn(cmask[2*r+1]);
            } else {
                int t = gr >= 2*Bn; int rem = gr - (t ? 2*Bn : 0);
                int j = rem >> 1, ck = rem & 1;
                int r = d_S.lvl[h][j];
                aptr0[it] = g_Hh + ((size_t)(t*512 + cidx[2*r+ck]))*1024 + ch*8;
                aptr1[it] = aptr0[it];
                am0[it] = __float2half2_rn(cmask[2*r+ck]);
                am1[it] = __float2half2_rn(0.f);
            }
        }
    }

    {   // zero-fill invalid A rows in all stages
        const uint4 zz = make_uint4(0,0,0,0);
        #pragma unroll
        for (int s = 0; s < 3; s++)
            #pragma unroll
            for (int it = 0; it < 2; it++)
                if (!avalid[it]) *(uint4*)&SA[s][arow[it]][ach[it]*4] = zz;
    }

    auto issueB = [&](int stage, int k0){
        int row = tid >> 2, ch = tid & 3;
        cpa16(baB + ((stage*64 + row)*20 + ch*4)*4,
              Bw + (size_t)(colBase + row)*1024 + k0 + ch*8);
        asm volatile("cp.async.commit_group;" ::: "memory");
    };

    float acc[2][4][4];
    #pragma unroll
    for (int i=0;i<2;i++) for (int j=0;j<4;j++) for (int e=0;e<4;e++) acc[i][j][e]=0.f;

    uint4 va[2];
    auto gatherA = [&](int k0){
        #pragma unroll
        for (int it = 0; it < 2; it++) {
            if (!avalid[it]) continue;
            uint4 u0 = *(const uint4*)(aptr0[it] + k0);
            uint4 u1 = *(const uint4*)(aptr1[it] + k0);
            __half2* a = (__half2*)&u0; __half2* b = (__half2*)&u1;
            uint4 r; __half2* o = (__half2*)&r;
            #pragma unroll
            for (int w = 0; w < 4; w++)
                o[w] = (which==0) ? __hfma2(b[w], am1[it], __hmul2(a[w], am0[it]))
                                  : __hmul2(a[w], am0[it]);
            va[it] = r;
        }
    };
    auto stsA = [&](int stage){
        #pragma unroll
        for (int it = 0; it < 2; it++)
            if (avalid[it]) *(uint4*)&SA[stage][arow[it]][ach[it]*4] = va[it];
    };

    gatherA(kbase);      stsA(0); issueB(0, kbase);
    gatherA(kbase + 32); stsA(1); issueB(1, kbase + 32);

    for (int c = 0; c < 16; c++) {
        const int stage = c % 3;
        const int kn = (c + 2) * 32;
        const int nst = (c + 2) % 3;
        if (kn < 512) gatherA(kbase + kn);
        if (kn < 512) { asm volatile("cp.async.wait_group 1;" ::: "memory"); }
        else          { asm volatile("cp.async.wait_group 0;" ::: "memory"); }
        __syncthreads();
        if (kn < 512) { stsA(nst); issueB(nst, kbase + kn); }
        #pragma unroll
        for (int s = 0; s < 2; s++) {
            const int kp = s*8;
            uint32_t a[2][4];
            #pragma unroll
            for (int i = 0; i < 2; i++) {
                int mb = wr*32 + i*16 + g;
                a[i][0] = SA[stage][mb    ][kp + tg];
                a[i][1] = SA[stage][mb + 8][kp + tg];
                a[i][2] = SA[stage][mb    ][kp + 4 + tg];
                a[i][3] = SA[stage][mb + 8][kp + 4 + tg];
            }
            uint32_t b[4][2];
            #pragma unroll
            for (int j = 0; j < 4; j++) {
                int nb = wc*32 + j*8 + g;
                b[j][0] = SB[stage][nb][kp + tg];
                b[j][1] = SB[stage][nb][kp + 4 + tg];
            }
            #pragma unroll
            for (int i = 0; i < 2; i++)
                #pragma unroll
                for (int j = 0; j < 4; j++)
                    mma_f16(acc[i][j], a[i][0], a[i][1], a[i][2], a[i][3],
                            b[j][0], b[j][1]);
        }
        __syncthreads();
    }

    #pragma unroll
    for (int i = 0; i < 2; i++)
        #pragma unroll
        for (int j = 0; j < 4; j++) {
            int r0 = rowBase + wr*32 + i*16 + g;
            int c0 = colBase + wc*32 + j*8 + tg*2;
            #pragma unroll
            for (int e = 0; e < 4; e++) {
                int row = r0 + ((e >> 1) ? 8 : 0);
                int col = c0 + (e & 1);
                if (row < Mrows)
                    Cout[(size_t)row*Nn + col] = acc[i][j][e];
            }
        }
}

// ---------------- persistent tree kernel: leaves + 9 levels, grid barriers ----------------
// __launch_bounds__(256, 2): 2 blocks/SM (regs capped at 128, smem 46KB x2 fits)
__global__ __launch_bounds__(256, 2)
void k_tree(const int* __restrict__ cidx, const float* __restrict__ cmask,
            const float* __restrict__ b_iouh, const float* __restrict__ b_fh)
{
    __shared__ uint32_t SA[3][128][20];
    __shared__ uint32_t SB[3][64][20];
    const int bid = blockIdx.x, tid = threadIdx.x;
    const int NB = gridDim.x;

    // ---- leaves ----
    for (int gid = bid*256 + tid; gid < 2*256*1024; gid += NB*256) {
        int i = gid >> 10, m = gid & 1023;
        int t = i >> 8, j = i & 255;
        int r = d_S.leaf[j];
        size_t x = (size_t)(t*512 + r);
        float ig = g_XALL[x*4096 + m]        + b_iouh[m];
        float og = g_XALL[x*4096 + 1024 + m] + b_iouh[1024 + m];
        float ug = g_XALL[x*4096 + 2048 + m] + b_iouh[2048 + m];
        float c = sigm(ig) * tanhf(ug);
        float hv = sigm(og) * tanhf(c);
        g_C[x*1024 + m] = c;
        g_H[x*1024 + m] = hv;
        g_Hh[x*1024 + m] = __float2half(hv);
    }
    grid_bar();

    // ---- internal levels ----
    for (int h = 1; h <= 15; h++) {
        int B = d_S.cnt[h];
        if (B == 0) continue;
        int my0 = (2*B + 127) >> 7;
        int my1 = (4*B + 127) >> 7;
        int T0 = 48*my0*2;
        int T  = T0 + 16*my1*2;
        for (int t = bid; t < T; t += NB) {
            int which, khalf, myi, col;
            if (t < T0) { which = 0; int r = t;      khalf = r & 1; r >>= 1; col = r % 48; myi = r / 48; }
            else        { which = 1; int r = t - T0; khalf = r & 1; r >>= 1; col = r & 15; myi = r >> 4; }
            do_lvl_tile(which, khalf, myi*128, col*64, h, B, cidx, cmask, SA, SB);
        }
        grid_bar();

        const size_t IOFF = (size_t)256*3072;
        const size_t FOFF = (size_t)512*1024;
        for (int gid = bid*256 + tid; gid < 2*B*1024; gid += NB*256) {
            int i = gid >> 10, m = gid & 1023;
            int t = i >= B; int j = i - (t ? B : 0);
            int r = d_S.lvl[h][j];
            size_t x = (size_t)(t*512 + r);
            // g_IOU/g_FP rows are REUSED across levels within this launch -> bypass L1
            float iou0 = __ldcg(&g_IOU[(size_t)i*3072 + m])        + __ldcg(&g_IOU[IOFF + (size_t)i*3072 + m]);
            float iou1 = __ldcg(&g_IOU[(size_t)i*3072 + 1024 + m]) + __ldcg(&g_IOU[IOFF + (size_t)i*3072 + 1024 + m]);
            float iou2 = __ldcg(&g_IOU[(size_t)i*3072 + 2048 + m]) + __ldcg(&g_IOU[IOFF + (size_t)i*3072 + 2048 + m]);
            float ig = g_XALL[x*4096 + m]        + iou0 + b_iouh[m];
            float og = g_XALL[x*4096 + 1024 + m] + iou1 + b_iouh[1024 + m];
            float ug = g_XALL[x*4096 + 2048 + m] + iou2 + b_iouh[2048 + m];
            float xf = g_XALL[x*4096 + 3072 + m];
            float fp0 = __ldcg(&g_FP[(size_t)(2*i  )*1024 + m]) + __ldcg(&g_FP[FOFF + (size_t)(2*i  )*1024 + m]);
            float fp1 = __ldcg(&g_FP[(size_t)(2*i+1)*1024 + m]) + __ldcg(&g_FP[FOFF + (size_t)(2*i+1)*1024 + m]);
            float f0 = sigm(fp0 + b_fh[m] + xf);
            float f1 = sigm(fp1 + b_fh[m] + xf);
            int c0 = cidx[2*r], c1 = cidx[2*r+1];
            float m0 = cmask[2*r], m1 = cmask[2*r+1];
            float cc0 = g_C[((size_t)(t*512 + c0))*1024 + m] * m0;
            float cc1 = g_C[((size_t)(t*512 + c1))*1024 + m] * m1;
            float c = sigm(ig)*tanhf(ug) + f0*cc0 + f1*cc1;
            float hv = sigm(og)*tanhf(c);
            g_C[x*1024 + m] = c;
            g_H[x*1024 + m] = hv;
            g_Hh[x*1024 + m] = __float2half(hv);
        }
        grid_bar();
    }
}

// ---------------- fp16 cp.async-pipelined GEMM (dense A), 128x64 tile ----
// MODE 0: A = g_Xh (M=1024), B = g_Wx (N=4096), C = g_XALL + split bias
// MODE 2: A = g_Hh (M=1024), B = g_Ws1h (N=256), C = tanh -> g_HB
template<int MODE>
__global__ __launch_bounds__(256)
void gemm_h(const float* __restrict__ b1, const float* __restrict__ b2)
{
    const __half* Aw = (MODE == 0) ? g_Xh : g_Hh;
    const __half* Bw = (MODE == 0) ? g_Wx : g_Ws1h;
    const int Nn = (MODE == 0) ? 4096 : 256;
    const int rowBase = blockIdx.y * 128;
    const int colBase = blockIdx.x * 64;

    __shared__ uint32_t SA[3][128][20];
    __shared__ uint32_t SB[3][64][20];

    const int tid  = threadIdx.x;
    const int lane = tid & 31, warp = tid >> 5;
    const int wr = warp >> 1, wc = warp & 1;
    const int g  = lane >> 2, tg = lane & 3;

    const uint32_t baA = smem_u32(&SA[0][0][0]);
    const uint32_t baB = smem_u32(&SB[0][0][0]);

    auto issue = [&](int stage, int k0){
        {
            int row = tid >> 2, ch = tid & 3;
            cpa16(baB + ((stage*64 + row)*20 + ch*4)*4,
                  Bw + (size_t)(colBase + row)*1024 + k0 + ch*8);
        }
        #pragma unroll
        for (int it = 0; it < 2; it++) {
            int idx = tid + (it << 8);
            int row = idx >> 2, ch = idx & 3;
            cpa16(baA + ((stage*128 + row)*20 + ch*4)*4,
                  Aw + (size_t)(rowBase + row)*1024 + k0 + ch*8);
        }
        asm volatile("cp.async.commit_group;" ::: "memory");
    };

    float acc[2][4][4];
    #pragma unroll
    for (int i=0;i<2;i++) for (int j=0;j<4;j++) for (int e=0;e<4;e++) acc[i][j][e]=0.f;

    issue(0, 0);
    issue(1, 32);

    for (int c = 0; c < 32; c++) {
        const int stage = c % 3;
        const int kn = (c + 2) * 32;
        const int nst = (c + 2) % 3;
        if (kn < 1024) { asm volatile("cp.async.wait_group 1;" ::: "memory"); }
        else           { asm volatile("cp.async.wait_group 0;" ::: "memory"); }
        __syncthreads();
        if (kn < 1024) issue(nst, kn);
        #pragma unroll
        for (int s = 0; s < 2; s++) {
            const int kp = s*8;
            uint32_t a[2][4];
            #pragma unroll
            for (int i = 0; i < 2; i++) {
                int mb = wr*32 + i*16 + g;
                a[i][0] = SA[stage][mb    ][kp + tg];
                a[i][1] = SA[stage][mb + 8][kp + tg];
                a[i][2] = SA[stage][mb    ][kp + 4 + tg];
                a[i][3] = SA[stage][mb + 8][kp + 4 + tg];
            }
            uint32_t b[4][2];
            #pragma unroll
            for (int j = 0; j < 4; j++) {
                int nb = wc*32 + j*8 + g;
                b[j][0] = SB[stage][nb][kp + tg];
                b[j][1] = SB[stage][nb][kp + 4 + tg];
            }
            #pragma unroll
            for (int i = 0; i < 2; i++)
                #pragma unroll
                for (int j = 0; j < 4; j++)
                    mma_f16(acc[i][j], a[i][0], a[i][1], a[i][2], a[i][3],
                            b[j][0], b[j][1]);
        }
        __syncthreads();
    }

    #pragma unroll
    for (int i = 0; i < 2; i++)
        #pragma unroll
        for (int j = 0; j < 4; j++) {
            int r0 = rowBase + wr*32 + i*16 + g;
            int c0 = colBase + wc*32 + j*8 + tg*2;
            #pragma unroll
            for (int e = 0; e < 4; e++) {
                int row = r0 + ((e >> 1) ? 8 : 0);
                int col = c0 + (e & 1);
                if (MODE == 0) {
                    float bias = (col < 3072) ? b1[col] : b2[col-3072];
                    g_XALL[(size_t)row*4096 + col] = acc[i][j][e] + bias;
                } else {
                    g_HB[(size_t)row*256 + col] = tanhf(acc[i][j][e]);
                }
            }
        }
}

// ---------------- tf32 small GEMM (ldA/ldB explicit; batched/split-K via z strides) ----
__device__ __forceinline__ uint32_t f2tf32(float x){
    uint32_t r;
    asm("cvt.rna.tf32.f32 %0, %1;" : "=r"(r) : "f"(x));
    return r;
}
__device__ __forceinline__ void mma_tf32(float c[4],
    uint32_t a0, uint32_t a1, uint32_t a2, uint32_t a3,
    uint32_t b0, uint32_t b1)
{
    asm volatile(
        "mma.sync.aligned.m16n8k8.row.col.f32.tf32.tf32.f32 "
        "{%0,%1,%2,%3}, {%4,%5,%6,%7}, {%8,%9}, {%0,%1,%2,%3};"
        : "+f"(c[0]), "+f"(c[1]), "+f"(c[2]), "+f"(c[3])
        : "r"(a0), "r"(a1), "r"(a2), "r"(a3), "r"(b0), "r"(b1));
}
__device__ __forceinline__ void sts_row(uint32_t S[][20], int row, int k4, float4 v){
    uint4 t;
    t.x = f2tf32(v.x); t.y = f2tf32(v.y);
    t.z = f2tf32(v.z); t.w = f2tf32(v.w);
    *(uint4*)&S[row][k4] = t;
}
__device__ __forceinline__ void mma_tile16(float acc[2][4][4],
        const uint32_t As[][20], const uint32_t Bs[][20],
        int wr, int wc, int g, int tg)
{
    #pragma unroll
    for (int ks = 0; ks < 16; ks += 8) {
        uint32_t a[2][4];
        #pragma unroll
        for (int i = 0; i < 2; i++) {
            int mb = wr*32 + i*16 + g;
            a[i][0] = As[mb    ][ks + tg];
            a[i][1] = As[mb + 8][ks + tg];
            a[i][2] = As[mb    ][ks + 4 + tg];
            a[i][3] = As[mb + 8][ks + 4 + tg];
        }
        uint32_t b[4][2];
        #pragma unroll
        for (int j = 0; j < 4; j++) {
            int nb = wc*32 + j*8 + g;
            b[j][0] = Bs[nb][ks + tg];
            b[j][1] = Bs[nb][ks + 4 + tg];
        }
        #pragma unroll
        for (int i = 0; i < 2; i++)
            #pragma unroll
            for (int j = 0; j < 4; j++)
                mma_tf32(acc[i][j], a[i][0], a[i][1], a[i][2], a[i][3],
                         b[j][0], b[j][1]);
    }
}

template<bool BT, int ACT>
__global__ __launch_bounds__(128) void gemm_s(
    const float* __restrict__ A, const float* __restrict__ B,
    const float* __restrict__ bias, float* __restrict__ C,
    int M, int N, int K, int ldA, int ldB,
    int sA, int sB, int sC)
{
    A += (size_t)blockIdx.z * sA;
    B += (size_t)blockIdx.z * sB;
    C += (size_t)blockIdx.z * sC;

    __shared__ uint32_t As[2][64][20];
    __shared__ uint32_t Bs[2][64][20];
    const int tid  = threadIdx.x;
    const int lane = tid & 31, warp = tid >> 5;
    const int wr = warp >> 1, wc = warp & 1;
    const int g = lane >> 2, tg = lane & 3;
    const int rowBase = blockIdx.y*64, colBase = blockIdx.x*64;

    float4 rA[2], rB[2];
    auto loadA = [&](int k0){
        #pragma unroll
        for (int it = 0; it < 2; it++) {
            int idx = tid + it*128, row = idx >> 2, k4 = (idx & 3)*4;
            int gr = rowBase + row;
            rA[it] = (gr < M) ? *(const float4*)(A + (size_t)gr*ldA + k0 + k4)
                              : make_float4(0.f,0.f,0.f,0.f);
        }
    };
    auto loadB = [&](int k0){
        #pragma unroll
        for (int it = 0; it < 2; it++) {
            int idx = tid + it*128;
            if (BT) {
                int row = idx >> 2, k4 = (idx & 3)*4;
                int gn = colBase + row;
                rB[it] = (gn < N) ? *(const float4*)(B + (size_t)gn*ldB + k0 + k4)
                                  : make_float4(0.f,0.f,0.f,0.f);
            } else {
                int k = idx >> 4, n4 = (idx & 15)*4;
                rB[it] = *(const float4*)(B + (size_t)(k0+k)*ldB + colBase + n4);
            }
        }
    };
    auto stsAll = [&](int buf){
        #pragma unroll
        for (int it = 0; it < 2; it++) {
            int idx = tid + it*128;
            int rowA = idx >> 2, k4 = (idx & 3)*4;
            sts_row(As[buf], rowA, k4, rA[it]);
            if (BT) {
                sts_row(Bs[buf], rowA, k4, rB[it]);
            } else {
                int k = idx >> 4, n4 = (idx & 15)*4;
                Bs[buf][n4+0][k] = f2tf32(rB[it].x);
                Bs[buf][n4+1][k] = f2tf32(rB[it].y);
                Bs[buf][n4+2][k] = f2tf32(rB[it].z);
                Bs[buf][n4+3][k] = f2tf32(rB[it].w);
            }
        }
    };

    float acc[2][4][4];
    #pragma unroll
    for (int i=0;i<2;i++) for (int j=0;j<4;j++) for (int e=0;e<4;e++) acc[i][j][e]=0.f;

    loadA(0); loadB(0); stsAll(0); __syncthreads();
    int buf = 0;
    for (int k0 = 16; ; k0 += 16) {
        bool more = (k0 < K);
        if (more) { loadA(k0); loadB(k0); }
        mma_tile16(acc, As[buf], Bs[buf], wr, wc, g, tg);
        if (!more) break;
        buf ^= 1;
        stsAll(buf);
        __syncthreads();
    }

    #pragma unroll
    for (int i = 0; i < 2; i++)
        #pragma unroll
        for (int j = 0; j < 4; j++) {
            int r0 = rowBase + wr*32 + i*16 + g;
            int c0 = colBase + wc*32 + j*8 + tg*2;
            #pragma unroll
            for (int e = 0; e < 4; e++) {
                int row = r0 + ((e >> 1) ? 8 : 0);
                int col = c0 + (e & 1);
                if (row < M && col < N) {
                    float v = acc[i][j][e];
                    if (bias) v += bias[col];
                    if (ACT == 1) v = tanhf(v);
                    else if (ACT == 2) v = fmaxf(v, 0.f);
                    C[(size_t)row*N + col] = v;
                }
            }
        }
}

// ---------------- pointwise kernels ----------------
__global__ void k_embed(const int* __restrict__ lin, const int* __restrict__ rin,
                        const float* __restrict__ emb)
{
    int row = blockIdx.x;
    int t = row >> 9, n = row & 511;
    int tok = t ? rin[n] : lin[n];
    float4 v = ((const float4*)(emb + (size_t)tok*1024))[threadIdx.x];
    ((uint2*)(g_Xh + (size_t)row*1024))[threadIdx.x] = f4_to_h4(v);
}

__global__ void k_soft(float* __restrict__ out)
{
    __shared__ float sh[512];
    int b = blockIdx.x;                 // t*16 + hop
    int t = b >> 4, hop = b & 15;
    int n = threadIdx.x;
    float v = g_LOG[(size_t)(t*512 + n)*16 + hop];
    sh[n] = v; __syncthreads();
    for (int s=256; s>0; s>>=1){ if (n < s) sh[n] = fmaxf(sh[n], sh[n+s]); __syncthreads(); }
    float mx = sh[0]; __syncthreads();
    float e = expf(v - mx);
    sh[n] = e; __syncthreads();
    for (int s=256; s>0; s>>=1){ if (n < s) sh[n] += sh[n+s]; __syncthreads(); }
    float a = e / sh[0];
    g_ALPHA[(size_t)b*512 + n] = a;
    out[5 + t*8192 + hop*512 + n] = a;
}

__global__ void k_lat(const float* __restrict__ w_lat, const float* __restrict__ b_lat)
{
    int m = blockIdx.x*256 + threadIdx.x;   // 1024
    float lv = b_lat[0], rv = b_lat[0];
    #pragma unroll
    for (int h=0; h<16; h++) {
        float w = w_lat[h];
        float sl = 0.f, sr = 0.f;
        #pragma unroll
        for (int z=0; z<4; z++) {
            sl += g_LSp[z*32768 + h*1024 + m];
            sr += g_LSp[z*32768 + (16 + h)*1024 + m];
        }
        lv += w * fmaxf(sl, 0.f);
        rv += w * fmaxf(sr, 0.f);
    }
    g_FR[m]        = fabsf(lv - rv);
    g_FR[1024 + m] = lv * rv;
    g_FR[2048 + m] = 0.5f * (lv + rv);
}

__global__ void k_fc(const float* __restrict__ w, const float* __restrict__ bb)
{
    int o = blockIdx.x*8 + (threadIdx.x >> 5);
    int lane = threadIdx.x & 31;
    const float* wr = w + (size_t)o*3072;
    float s = 0.f;
    for (int k=lane; k<3072; k+=32) s += g_FR[k]*wr[k];
    for (int d=16; d; d>>=1) s += __shfl_down_sync(0xffffffffu, s, d);
    if (!lane) { float v = s + bb[o]; g_FC[o] = v > 0.f ? v : 0.01f*v; }
}

__global__ void k_fc2out(const float* __restrict__ w_out, const float* __restrict__ b_out,
                         const float* __restrict__ w_out1, const float* __restrict__ b_out1,
                         float* __restrict__ out)
{
    __shared__ float fc2[256];
    __shared__ float logit[5];
    int tid = threadIdx.x;             // 256
    int wid = tid >> 5, lane = tid & 31;
    for (int it = 0; it < 4; it++) {
        int o = wid*32 + (it << 3) + (lane >> 2);
        float s = 0.f;
        for (int k = (lane & 3); k < 512; k += 4) s += g_FC[k]*w_out[(size_t)o*512 + k];
        s += __shfl_down_sync(0xffffffffu, s, 2);
        s += __shfl_down_sync(0xffffffffu, s, 1);
        if ((lane & 3) == 0) fc2[o] = sigm(s + b_out[o]);
    }
    __syncthreads();
    if (wid < 5) {
        float s = 0.f;
        for (int k = lane; k < 256; k += 32) s += fc2[k]*w_out1[wid*256 + k];
        for (int d = 16; d; d >>= 1) s += __shfl_down_sync(0xffffffffu, s, d);
        if (!lane) logit[wid] = s + b_out1[wid];
    }
    __syncthreads();
    if (tid == 0) {
        float mx = logit[0];
        for (int c=1;c<5;c++) mx = fmaxf(mx, logit[c]);
        float sum = 0.f;
        for (int c=0;c<5;c++) sum += expf(logit[c]-mx);
        float l = logf(sum);
        for (int c=0;c<5;c++) out[c] = logit[c] - mx - l;
    }
}

// ---------------- launch ----------------
extern "C" void kernel_launch(void* const* d_in, const int* in_sizes, int n_in,
                              void* d_out, int out_size)
{
    const int*   linputs    = (const int*)  d_in[0];
    const int*   rinputs    = (const int*)  d_in[1];
    const int*   child_idx  = (const int*)  d_in[2];
    const float* child_mask = (const float*)d_in[3];
    const float* emb        = (const float*)d_in[4];
    const float* w_ioux     = (const float*)d_in[5];
    const float* b_ioux     = (const float*)d_in[6];
    const float* w_iouh     = (const float*)d_in[7];
    const float* b_iouh     = (const float*)d_in[8];
    const float* w_fx       = (const float*)d_in[9];
    const float* b_fx       = (const float*)d_in[10];
    const float* w_fh       = (const float*)d_in[11];
    const float* b_fh       = (const float*)d_in[12];
    const float* ws1        = (const float*)d_in[13];
    const float* ws2        = (const float*)d_in[14];
    const float* wf         = (const float*)d_in[15];
    const float* w_lat      = (const float*)d_in[16];
    const float* b_lat      = (const float*)d_in[17];
    const float* w_fc       = (const float*)d_in[18];
    const float* b_fc       = (const float*)d_in[19];
    const float* w_out      = (const float*)d_in[20];
    const float* b_out      = (const float*)d_in[21];
    const float* w_out1     = (const float*)d_in[22];
    const float* b_out1     = (const float*)d_in[23];
    float* out = (float*)d_out;

    float *pH, *pHB, *pLOG, *pALPHA, *pM, *pLSp;
    cudaGetSymbolAddress((void**)&pH,     g_H);
    cudaGetSymbolAddress((void**)&pHB,    g_HB);
    cudaGetSymbolAddress((void**)&pLOG,   g_LOG);
    cudaGetSymbolAddress((void**)&pALPHA, g_ALPHA);
    cudaGetSymbolAddress((void**)&pM,     g_Mm);
    cudaGetSymbolAddress((void**)&pLSp,   g_LSp);

    // Size the persistent grid for guaranteed co-residency (deadlock-safe).
    static int nTreeBlk = 0;
    if (nTreeBlk == 0) {
        int perSM = 0, sms = 0, dev = 0;
        cudaGetDevice(&dev);
        cudaDeviceGetAttribute(&sms, cudaDevAttrMultiProcessorCount, dev);
        cudaOccupancyMaxActiveBlocksPerMultiprocessor(&perSM, k_tree, 256, 0);
        if (perSM < 1) perSM = 1;
        if (perSM > 2) perSM = 2;
        if (sms < 1) sms = 148;
        nTreeBlk = perSM * sms;
    }

    // 0) weight conversion to half
    k_cvtW<<<8448, 256>>>(w_ioux, w_fx, w_iouh, w_fh, ws1);

    // 1) embedding gather (half)
    k_embed<<<1024, 256>>>(linputs, rinputs, emb);

    // 2) fused input projections: M=1024, N=4096, K=1024
    gemm_h<0><<<dim3(64, 8, 1), 256>>>(b_ioux, b_fx);

    // 3) persistent kernel: leaves + all internal levels (grid barriers)
    k_tree<<<nTreeBlk, 256>>>(child_idx, child_mask, b_iouh, b_fh);

    // 4) attention
    gemm_h<2><<<dim3(4, 8, 1), 256>>>(nullptr, nullptr);
    gemm_s<true,0><<<dim3(1,16,1), 128>>>(pHB, ws2, nullptr, pLOG,
                                          1024, 16, 256, 256, 256, 0, 0, 0);
    k_soft<<<32, 512>>>(out);
    gemm_s<false,0><<<dim3(16,1,2), 128>>>(pALPHA, pH, nullptr, pM,
                                           16, 1024, 512, 512, 1024,
                                           16*512, 512*1024, 16*1024);

    // 5) head: wf GEMM split-K=4 (K slabs of 256), relu folded into k_lat
    gemm_s<false,0><<<dim3(16,1,4), 128>>>(pM, wf, nullptr, pLSp,
                                           32, 1024, 256, 1024, 1024,
                                           256, 256*1024, 32*1024);
    k_lat<<<4, 256>>>(w_lat, b_lat);
    k_fc<<<64, 256>>>(w_fc, b_fc);
    k_fc2out<<<1, 256>>>(w_out, b_out, w_out1, b_out1, out);
}

// round 17
// speedup vs baseline: 1.1861x; 1.0933x over previous
#include <cuda_runtime.h>
#include <cuda_fp16.h>
#include <math.h>
#include <stdint.h>

// ---------------- static device scratch ----------------
__device__ __align__(16) float g_XALL[2*512*4096];   // [iou(3072) | f(1024)] per row
__device__ __align__(16) float g_H[2*512*1024];
__device__ __align__(16) float g_C[2*512*1024];
__device__ __align__(16) float g_IOU[4*256*3072];    // four split-K partials
__device__ __align__(16) float g_FP[4*512*1024];     // four split-K partials
__device__ __align__(16) float g_HB[1024*256];
__device__ __align__(16) float g_LOG[1024*16];
__device__ __align__(16) float g_ALPHA[2*16*512];
__device__ __align__(16) float g_Mm[32*1024];
__device__ __align__(16) float g_LSp[4*32*1024];     // wf split-K partials
__device__ __align__(16) float g_FR[3072];
__device__ __align__(16) float g_FC[512];
// half-precision operand copies
__device__ __align__(16) __half g_Wx[4096*1024];     // [w_ioux rows | w_fx rows]
__device__ __align__(16) __half g_Wiouh[3072*1024];
__device__ __align__(16) __half g_Wfh[1024*1024];
__device__ __align__(16) __half g_Ws1h[256*1024];
__device__ __align__(16) __half g_Xh[1024*1024];
__device__ __align__(16) __half g_Hh[2*512*1024];

// ---------------- compile-time tree schedule (N=512 heap, DFS post-order) ----------------
struct Sched {
    int leaf[256];
    int cnt[16];
    int lvl[16][128];
};

constexpr Sched make_sched() {
    Sched s{};
    int order[512] = {}; int rankOf[512] = {}; int height[512] = {};
    int stN[64] = {}; int stP[64] = {};
    int sp = 1, cnt = 0;
    stN[0] = 0; stP[0] = 0;
    while (sp) {
        int j = stN[sp-1], p = stP[sp-1];
        if (p < 2) {
            stP[sp-1] = p + 1;
            int c = 2*j + 1 + p;
            if (c < 512) { stN[sp] = c; stP[sp] = 0; sp++; }
        } else { order[cnt] = j; rankOf[j] = cnt; cnt++; sp--; }
    }
    int nleaf = 0;
    for (int r = 0; r < 512; r++) {
        int j = order[r]; int h = 0;
        for (int k = 0; k < 2; k++) {
            int c = 2*j + 1 + k;
            if (c < 512) { int hh = height[rankOf[c]] + 1; if (hh > h) h = hh; }
        }
        height[r] = h;
        if (h == 0) s.leaf[nleaf++] = r;
        else        s.lvl[h][s.cnt[h]++] = r;
    }
    return s;
}

__device__ const Sched d_S = make_sched();

__device__ __forceinline__ float sigm(float x){ return 1.f/(1.f+expf(-x)); }

__device__ __forceinline__ uint2 f4_to_h4(float4 v){
    __half2 p0 = __floats2half2_rn(v.x, v.y);
    __half2 p1 = __floats2half2_rn(v.z, v.w);
    uint2 r; r.x = *(uint32_t*)&p0; r.y = *(uint32_t*)&p1;
    return r;
}

__device__ __forceinline__ uint32_t smem_u32(const void* p){
    uint32_t a;
    asm("{ .reg .u64 t; cvta.to.shared.u64 t, %1; cvt.u32.u64 %0, t; }" : "=r"(a) : "l"(p));
    return a;
}
__device__ __forceinline__ void cpa16(uint32_t dst, const void* src){
    asm volatile("cp.async.cg.shared.global [%0], [%1], 16;" :: "r"(dst), "l"(src));
}

__device__ __forceinline__ void mma_f16(float c[4],
    uint32_t a0, uint32_t a1, uint32_t a2, uint32_t a3,
    uint32_t b0, uint32_t b1)
{
    asm volatile(
        "mma.sync.aligned.m16n8k16.row.col.f32.f16.f16.f32 "
        "{%0,%1,%2,%3}, {%4,%5,%6,%7}, {%8,%9}, {%0,%1,%2,%3};"
        : "+f"(c[0]), "+f"(c[1]), "+f"(c[2]), "+f"(c[3])
        : "r"(a0), "r"(a1), "r"(a2), "r"(a3), "r"(b0), "r"(b1));
}

// ---------------- grid-wide barrier (grid sized for guaranteed co-residency) ----------------
__device__ unsigned g_barCnt = 0;
__device__ volatile unsigned g_barGen = 0;

__device__ __forceinline__ void grid_bar()
{
    __syncthreads();
    if (threadIdx.x == 0) {
        unsigned gen = g_barGen;
        __threadfence();
        if (atomicAdd(&g_barCnt, 1u) == gridDim.x - 1u) {
            g_barCnt = 0u;
            __threadfence();
            g_barGen = gen + 1u;
        } else {
            while (g_barGen == gen) __nanosleep(64);
        }
    }
    __syncthreads();
}

// ---------------- weight pre-conversion (fp32 -> half), flat ----------------
// cumulative float4 groups: 786432 / 1048576 / 1835008 / 2097152 / 2162688
__global__ void k_cvtW(const float* __restrict__ w_ioux, const float* __restrict__ w_fx,
                       const float* __restrict__ w_iouh, const float* __restrict__ w_fh,
                       const float* __restrict__ ws1)
{
    int i = blockIdx.x*256 + threadIdx.x;
    if (i >= 2162688) return;
    const float4* src; uint2* dst;
    if (i < 786432)       { src = (const float4*)w_ioux + i;            dst = (uint2*)g_Wx + i; }
    else if (i < 1048576) { int j = i -  786432; src = (const float4*)w_fx   + j; dst = (uint2*)g_Wx + 786432 + j; }
    else if (i < 1835008) { int j = i - 1048576; src = (const float4*)w_iouh + j; dst = (uint2*)g_Wiouh + j; }
    else if (i < 2097152) { int j = i - 1835008; src = (const float4*)w_fh   + j; dst = (uint2*)g_Wfh + j; }
    else                  { int j = i - 2097152; src = (const float4*)ws1    + j; dst = (uint2*)g_Ws1h + j; }
    *dst = f4_to_h4(*src);
}

// ---------------- level GEMM tile (fp16, cp.async B, gathered A, K-quarter 256) ----------------
__device__ void do_lvl_tile(
    int which, int kq, int rowBase, int colBase, int h, int Bn,
    const int* __restrict__ cidx, const float* __restrict__ cmask,
    uint32_t SA[3][128][20], uint32_t SB[3][64][20])
{
    const int Mrows = which ? 4*Bn : 2*Bn;
    const int Nn    = which ? 1024 : 3072;
    const __half* Bw = which ? g_Wfh : g_Wiouh;
    float* Cout = which ? (g_FP + (size_t)kq*512*1024)
                        : (g_IOU + (size_t)kq*256*3072);
    const int kbase = kq * 256;

    const int tid  = threadIdx.x;
    const int lane = tid & 31, warp = tid >> 5;
    const int wr = warp >> 1, wc = warp & 1;
    const int g  = lane >> 2, tg = lane & 3;
    const uint32_t baB = smem_u32(&SB[0][0][0]);

    const __half* aptr0[2]; const __half* aptr1[2];
    __half2 am0[2], am1[2]; bool avalid[2]; int arow[2], ach[2];
    #pragma unroll
    for (int it = 0; it < 2; it++) {
        int idx = tid + (it << 8);
        int row = idx >> 2, ch = idx & 3;
        arow[it] = row; ach[it] = ch;
        int gr = rowBase + row;
        avalid[it] = (gr < Mrows);
        if (avalid[it]) {
            if (which == 0) {
                int t = gr >= Bn; int j = gr - (t ? Bn : 0);
                int r = d_S.lvl[h][j];
                aptr0[it] = g_Hh + ((size_t)(t*512 + cidx[2*r  ]))*1024 + ch*8;
                aptr1[it] = g_Hh + ((size_t)(t*512 + cidx[2*r+1]))*1024 + ch*8;
                am0[it] = __float2half2_rn(cmask[2*r]);
                am1[it] = __float2half2_rn(cmask[2*r+1]);
            } else {
                int t = gr >= 2*Bn; int rem = gr - (t ? 2*Bn : 0);
                int j = rem >> 1, ck = rem & 1;
                int r = d_S.lvl[h][j];
                aptr0[it] = g_Hh + ((size_t)(t*512 + cidx[2*r+ck]))*1024 + ch*8;
                aptr1[it] = aptr0[it];
                am0[it] = __float2half2_rn(cmask[2*r+ck]);
                am1[it] = __float2half2_rn(0.f);
            }
        }
    }

    {   // zero-fill invalid A rows in all stages
        const uint4 zz = make_uint4(0,0,0,0);
        #pragma unroll
        for (int s = 0; s < 3; s++)
            #pragma unroll
            for (int it = 0; it < 2; it++)
                if (!avalid[it]) *(uint4*)&SA[s][arow[it]][ach[it]*4] = zz;
    }

    auto issueB = [&](int stage, int k0){
        int row = tid >> 2, ch = tid & 3;
        cpa16(baB + ((stage*64 + row)*20 + ch*4)*4,
              Bw + (size_t)(colBase + row)*1024 + k0 + ch*8);
        asm volatile("cp.async.commit_group;" ::: "memory");
    };

    float acc[2][4][4];
    #pragma unroll
    for (int i=0;i<2;i++) for (int j=0;j<4;j++) for (int e=0;e<4;e++) acc[i][j][e]=0.f;

    uint4 va[2];
    auto gatherA = [&](int k0){
        #pragma unroll
        for (int it = 0; it < 2; it++) {
            if (!avalid[it]) continue;
            uint4 u0 = *(const uint4*)(aptr0[it] + k0);
            uint4 u1 = *(const uint4*)(aptr1[it] + k0);
            __half2* a = (__half2*)&u0; __half2* b = (__half2*)&u1;
            uint4 r; __half2* o = (__half2*)&r;
            #pragma unroll
            for (int w = 0; w < 4; w++)
                o[w] = (which==0) ? __hfma2(b[w], am1[it], __hmul2(a[w], am0[it]))
                                  : __hmul2(a[w], am0[it]);
            va[it] = r;
        }
    };
    auto stsA = [&](int stage){
        #pragma unroll
        for (int it = 0; it < 2; it++)
            if (avalid[it]) *(uint4*)&SA[stage][arow[it]][ach[it]*4] = va[it];
    };

    gatherA(kbase);      stsA(0); issueB(0, kbase);
    gatherA(kbase + 32); stsA(1); issueB(1, kbase + 32);

    for (int c = 0; c < 8; c++) {
        const int stage = c % 3;
        const int kn = (c + 2) * 32;
        const int nst = (c + 2) % 3;
        if (kn < 256) gatherA(kbase + kn);
        if (kn < 256) { asm volatile("cp.async.wait_group 1;" ::: "memory"); }
        else          { asm volatile("cp.async.wait_group 0;" ::: "memory"); }
        __syncthreads();
        if (kn < 256) { stsA(nst); issueB(nst, kbase + kn); }
        #pragma unroll
        for (int s = 0; s < 2; s++) {
            const int kp = s*8;
            uint32_t a[2][4];
            #pragma unroll
            for (int i = 0; i < 2; i++) {
                int mb = wr*32 + i*16 + g;
                a[i][0] = SA[stage][mb    ][kp + tg];
                a[i][1] = SA[stage][mb + 8][kp + tg];
                a[i][2] = SA[stage][mb    ][kp + 4 + tg];
                a[i][3] = SA[stage][mb + 8][kp + 4 + tg];
            }
            uint32_t b[4][2];
            #pragma unroll
            for (int j = 0; j < 4; j++) {
                int nb = wc*32 + j*8 + g;
                b[j][0] = SB[stage][nb][kp + tg];
                b[j][1] = SB[stage][nb][kp + 4 + tg];
            }
            #pragma unroll
            for (int i = 0; i < 2; i++)
                #pragma unroll
                for (int j = 0; j < 4; j++)
                    mma_f16(acc[i][j], a[i][0], a[i][1], a[i][2], a[i][3],
                            b[j][0], b[j][1]);
        }
        __syncthreads();
    }

    #pragma unroll
    for (int i = 0; i < 2; i++)
        #pragma unroll
        for (int j = 0; j < 4; j++) {
            int r0 = rowBase + wr*32 + i*16 + g;
            int c0 = colBase + wc*32 + j*8 + tg*2;
            #pragma unroll
            for (int e = 0; e < 4; e++) {
                int row = r0 + ((e >> 1) ? 8 : 0);
                int col = c0 + (e & 1);
                if (row < Mrows)
                    Cout[(size_t)row*Nn + col] = acc[i][j][e];
            }
        }
}

// ---------------- persistent tree kernel: leaves + 9 levels, grid barriers ----------------
// __launch_bounds__(256, 2): 2 blocks/SM (regs capped at 128, smem 46KB x2 fits)
__global__ __launch_bounds__(256, 2)
void k_tree(const int* __restrict__ cidx, const float* __restrict__ cmask,
            const float* __restrict__ b_iouh, const float* __restrict__ b_fh)
{
    __shared__ uint32_t SA[3][128][20];
    __shared__ uint32_t SB[3][64][20];
    const int bid = blockIdx.x, tid = threadIdx.x;
    const int NB = gridDim.x;

    // ---- leaves ----
    for (int gid = bid*256 + tid; gid < 2*256*1024; gid += NB*256) {
        int i = gid >> 10, m = gid & 1023;
        int t = i >> 8, j = i & 255;
        int r = d_S.leaf[j];
        size_t x = (size_t)(t*512 + r);
        float ig = g_XALL[x*4096 + m]        + b_iouh[m];
        float og = g_XALL[x*4096 + 1024 + m] + b_iouh[1024 + m];
        float ug = g_XALL[x*4096 + 2048 + m] + b_iouh[2048 + m];
        float c = sigm(ig) * tanhf(ug);
        float hv = sigm(og) * tanhf(c);
        g_C[x*1024 + m] = c;
        g_H[x*1024 + m] = hv;
        g_Hh[x*1024 + m] = __float2half(hv);
    }
    grid_bar();

    // ---- internal levels ----
    for (int h = 1; h <= 15; h++) {
        int B = d_S.cnt[h];
        if (B == 0) continue;
        int my0 = (2*B + 127) >> 7;
        int my1 = (4*B + 127) >> 7;
        int T0 = 48*my0*4;
        int T  = T0 + 16*my1*4;
        for (int t = bid; t < T; t += NB) {
            int which, kq, myi, col;
            if (t < T0) { which = 0; int r = t;      kq = r & 3; r >>= 2; col = r % 48; myi = r / 48; }
            else        { which = 1; int r = t - T0; kq = r & 3; r >>= 2; col = r & 15; myi = r >> 4; }
            do_lvl_tile(which, kq, myi*128, col*64, h, B, cidx, cmask, SA, SB);
        }
        grid_bar();

        const size_t IOFF = (size_t)256*3072;
        const size_t FOFF = (size_t)512*1024;
        for (int gid = bid*256 + tid; gid < 2*B*1024; gid += NB*256) {
            int i = gid >> 10, m = gid & 1023;
            int t = i >= B; int j = i - (t ? B : 0);
            int r = d_S.lvl[h][j];
            size_t x = (size_t)(t*512 + r);
            // g_IOU/g_FP rows are REUSED across levels within this launch -> bypass L1
            float iou0 = 0.f, iou1 = 0.f, iou2 = 0.f, fp0 = 0.f, fp1 = 0.f;
            #pragma unroll
            for (int z = 0; z < 4; z++) {
                iou0 += __ldcg(&g_IOU[z*IOFF + (size_t)i*3072 + m]);
                iou1 += __ldcg(&g_IOU[z*IOFF + (size_t)i*3072 + 1024 + m]);
                iou2 += __ldcg(&g_IOU[z*IOFF + (size_t)i*3072 + 2048 + m]);
                fp0  += __ldcg(&g_FP[z*FOFF + (size_t)(2*i  )*1024 + m]);
                fp1  += __ldcg(&g_FP[z*FOFF + (size_t)(2*i+1)*1024 + m]);
            }
            float ig = g_XALL[x*4096 + m]        + iou0 + b_iouh[m];
            float og = g_XALL[x*4096 + 1024 + m] + iou1 + b_iouh[1024 + m];
            float ug = g_XALL[x*4096 + 2048 + m] + iou2 + b_iouh[2048 + m];
            float xf = g_XALL[x*4096 + 3072 + m];
            float f0 = sigm(fp0 + b_fh[m] + xf);
            float f1 = sigm(fp1 + b_fh[m] + xf);
            int c0 = cidx[2*r], c1 = cidx[2*r+1];
            float m0 = cmask[2*r], m1 = cmask[2*r+1];
            float cc0 = g_C[((size_t)(t*512 + c0))*1024 + m] * m0;
            float cc1 = g_C[((size_t)(t*512 + c1))*1024 + m] * m1;
            float c = sigm(ig)*tanhf(ug) + f0*cc0 + f1*cc1;
            float hv = sigm(og)*tanhf(c);
            g_C[x*1024 + m] = c;
            g_H[x*1024 + m] = hv;
            g_Hh[x*1024 + m] = __float2half(hv);
        }
        grid_bar();
    }
}

// ---------------- fp16 cp.async-pipelined GEMM (dense A), 128x64 tile ----
// MODE 0: A = g_Xh (M=1024), B = g_Wx (N=4096), C = g_XALL + split bias
// MODE 2: A = g_Hh (M=1024), B = g_Ws1h (N=256), C = tanh -> g_HB
template<int MODE>
__global__ __launch_bounds__(256)
void gemm_h(const float* __restrict__ b1, const float* __restrict__ b2)
{
    const __half* Aw = (MODE == 0) ? g_Xh : g_Hh;
    const __half* Bw = (MODE == 0) ? g_Wx : g_Ws1h;
    const int Nn = (MODE == 0) ? 4096 : 256;
    const int rowBase = blockIdx.y * 128;
    const int colBase = blockIdx.x * 64;

    __shared__ uint32_t SA[3][128][20];
    __shared__ uint32_t SB[3][64][20];

    const int tid  = threadIdx.x;
    const int lane = tid & 31, warp = tid >> 5;
    const int wr = warp >> 1, wc = warp & 1;
    const int g  = lane >> 2, tg = lane & 3;

    const uint32_t baA = smem_u32(&SA[0][0][0]);
    const uint32_t baB = smem_u32(&SB[0][0][0]);

    auto issue = [&](int stage, int k0){
        {
            int row = tid >> 2, ch = tid & 3;
            cpa16(baB + ((stage*64 + row)*20 + ch*4)*4,
                  Bw + (size_t)(colBase + row)*1024 + k0 + ch*8);
        }
        #pragma unroll
        for (int it = 0; it < 2; it++) {
            int idx = tid + (it << 8);
            int row = idx >> 2, ch = idx & 3;
            cpa16(baA + ((stage*128 + row)*20 + ch*4)*4,
                  Aw + (size_t)(rowBase + row)*1024 + k0 + ch*8);
        }
        asm volatile("cp.async.commit_group;" ::: "memory");
    };

    float acc[2][4][4];
    #pragma unroll
    for (int i=0;i<2;i++) for (int j=0;j<4;j++) for (int e=0;e<4;e++) acc[i][j][e]=0.f;

    issue(0, 0);
    issue(1, 32);

    for (int c = 0; c < 32; c++) {
        const int stage = c % 3;
        const int kn = (c + 2) * 32;
        const int nst = (c + 2) % 3;
        if (kn < 1024) { asm volatile("cp.async.wait_group 1;" ::: "memory"); }
        else           { asm volatile("cp.async.wait_group 0;" ::: "memory"); }
        __syncthreads();
        if (kn < 1024) issue(nst, kn);
        #pragma unroll
        for (int s = 0; s < 2; s++) {
            const int kp = s*8;
            uint32_t a[2][4];
            #pragma unroll
            for (int i = 0; i < 2; i++) {
                int mb = wr*32 + i*16 + g;
                a[i][0] = SA[stage][mb    ][kp + tg];
                a[i][1] = SA[stage][mb + 8][kp + tg];
                a[i][2] = SA[stage][mb    ][kp + 4 + tg];
                a[i][3] = SA[stage][mb + 8][kp + 4 + tg];
            }
            uint32_t b[4][2];
            #pragma unroll
            for (int j = 0; j < 4; j++) {
                int nb = wc*32 + j*8 + g;
                b[j][0] = SB[stage][nb][kp + tg];
                b[j][1] = SB[stage][nb][kp + 4 + tg];
            }
            #pragma unroll
            for (int i = 0; i < 2; i++)
                #pragma unroll
                for (int j = 0; j < 4; j++)
                    mma_f16(acc[i][j], a[i][0], a[i][1], a[i][2], a[i][3],
                            b[j][0], b[j][1]);
        }
        __syncthreads();
    }

    #pragma unroll
    for (int i = 0; i < 2; i++)
        #pragma unroll
        for (int j = 0; j < 4; j++) {
            int r0 = rowBase + wr*32 + i*16 + g;
            int c0 = colBase + wc*32 + j*8 + tg*2;
            #pragma unroll
            for (int e = 0; e < 4; e++) {
                int row = r0 + ((e >> 1) ? 8 : 0);
                int col = c0 + (e & 1);
                if (MODE == 0) {
                    float bias = (col < 3072) ? b1[col] : b2[col-3072];
                    g_XALL[(size_t)row*4096 + col] = acc[i][j][e] + bias;
                } else {
                    g_HB[(size_t)row*256 + col] = tanhf(acc[i][j][e]);
                }
            }
        }
}

// ---------------- tf32 small GEMM (ldA/ldB explicit; batched/split-K via z strides) ----
__device__ __forceinline__ uint32_t f2tf32(float x){
    uint32_t r;
    asm("cvt.rna.tf32.f32 %0, %1;" : "=r"(r) : "f"(x));
    return r;
}
__device__ __forceinline__ void mma_tf32(float c[4],
    uint32_t a0, uint32_t a1, uint32_t a2, uint32_t a3,
    uint32_t b0, uint32_t b1)
{
    asm volatile(
        "mma.sync.aligned.m16n8k8.row.col.f32.tf32.tf32.f32 "
        "{%0,%1,%2,%3}, {%4,%5,%6,%7}, {%8,%9}, {%0,%1,%2,%3};"
        : "+f"(c[0]), "+f"(c[1]), "+f"(c[2]), "+f"(c[3])
        : "r"(a0), "r"(a1), "r"(a2), "r"(a3), "r"(b0), "r"(b1));
}
__device__ __forceinline__ void sts_row(uint32_t S[][20], int row, int k4, float4 v){
    uint4 t;
    t.x = f2tf32(v.x); t.y = f2tf32(v.y);
    t.z = f2tf32(v.z); t.w = f2tf32(v.w);
    *(uint4*)&S[row][k4] = t;
}
__device__ __forceinline__ void mma_tile16(float acc[2][4][4],
        const uint32_t As[][20], const uint32_t Bs[][20],
        int wr, int wc, int g, int tg)
{
    #pragma unroll
    for (int ks = 0; ks < 16; ks += 8) {
        uint32_t a[2][4];
        #pragma unroll
        for (int i = 0; i < 2; i++) {
            int mb = wr*32 + i*16 + g;
            a[i][0] = As[mb    ][ks + tg];
            a[i][1] = As[mb + 8][ks + tg];
            a[i][2] = As[mb    ][ks + 4 + tg];
            a[i][3] = As[mb + 8][ks + 4 + tg];
        }
        uint32_t b[4][2];
        #pragma unroll
        for (int j = 0; j < 4; j++) {
            int nb = wc*32 + j*8 + g;
            b[j][0] = Bs[nb][ks + tg];
            b[j][1] = Bs[nb][ks + 4 + tg];
        }
        #pragma unroll
        for (int i = 0; i < 2; i++)
            #pragma unroll
            for (int j = 0; j < 4; j++)
                mma_tf32(acc[i][j], a[i][0], a[i][1], a[i][2], a[i][3],
                         b[j][0], b[j][1]);
    }
}

template<bool BT, int ACT>
__global__ __launch_bounds__(128) void gemm_s(
    const float* __restrict__ A, const float* __restrict__ B,
    const float* __restrict__ bias, float* __restrict__ C,
    int M, int N, int K, int ldA, int ldB,
    int sA, int sB, int sC)
{
    A += (size_t)blockIdx.z * sA;
    B += (size_t)blockIdx.z * sB;
    C += (size_t)blockIdx.z * sC;

    __shared__ uint32_t As[2][64][20];
    __shared__ uint32_t Bs[2][64][20];
    const int tid  = threadIdx.x;
    const int lane = tid & 31, warp = tid >> 5;
    const int wr = warp >> 1, wc = warp & 1;
    const int g = lane >> 2, tg = lane & 3;
    const int rowBase = blockIdx.y*64, colBase = blockIdx.x*64;

    float4 rA[2], rB[2];
    auto loadA = [&](int k0){
        #pragma unroll
        for (int it = 0; it < 2; it++) {
            int idx = tid + it*128, row = idx >> 2, k4 = (idx & 3)*4;
            int gr = rowBase + row;
            rA[it] = (gr < M) ? *(const float4*)(A + (size_t)gr*ldA + k0 + k4)
                              : make_float4(0.f,0.f,0.f,0.f);
        }
    };
    auto loadB = [&](int k0){
        #pragma unroll
        for (int it = 0; it < 2; it++) {
            int idx = tid + it*128;
            if (BT) {
                int row = idx >> 2, k4 = (idx & 3)*4;
                int gn = colBase + row;
                rB[it] = (gn < N) ? *(const float4*)(B + (size_t)gn*ldB + k0 + k4)
                                  : make_float4(0.f,0.f,0.f,0.f);
            } else {
                int k = idx >> 4, n4 = (idx & 15)*4;
                rB[it] = *(const float4*)(B + (size_t)(k0+k)*ldB + colBase + n4);
            }
        }
    };
    auto stsAll = [&](int buf){
        #pragma unroll
        for (int it = 0; it < 2; it++) {
            int idx = tid + it*128;
            int rowA = idx >> 2, k4 = (idx & 3)*4;
            sts_row(As[buf], rowA, k4, rA[it]);
            if (BT) {
                sts_row(Bs[buf], rowA, k4, rB[it]);
            } else {
                int k = idx >> 4, n4 = (idx & 15)*4;
                Bs[buf][n4+0][k] = f2tf32(rB[it].x);
                Bs[buf][n4+1][k] = f2tf32(rB[it].y);
                Bs[buf][n4+2][k] = f2tf32(rB[it].z);
                Bs[buf][n4+3][k] = f2tf32(rB[it].w);
            }
        }
    };

    float acc[2][4][4];
    #pragma unroll
    for (int i=0;i<2;i++) for (int j=0;j<4;j++) for (int e=0;e<4;e++) acc[i][j][e]=0.f;

    loadA(0); loadB(0); stsAll(0); __syncthreads();
    int buf = 0;
    for (int k0 = 16; ; k0 += 16) {
        bool more = (k0 < K);
        if (more) { loadA(k0); loadB(k0); }
        mma_tile16(acc, As[buf], Bs[buf], wr, wc, g, tg);
        if (!more) break;
        buf ^= 1;
        stsAll(buf);
        __syncthreads();
    }

    #pragma unroll
    for (int i = 0; i < 2; i++)
        #pragma unroll
        for (int j = 0; j < 4; j++) {
            int r0 = rowBase + wr*32 + i*16 + g;
            int c0 = colBase + wc*32 + j*8 + tg*2;
            #pragma unroll
            for (int e = 0; e < 4; e++) {
                int row = r0 + ((e >> 1) ? 8 : 0);
                int col = c0 + (e & 1);
                if (row < M && col < N) {
                    float v = acc[i][j][e];
                    if (bias) v += bias[col];
                    if (ACT == 1) v = tanhf(v);
                    else if (ACT == 2) v = fmaxf(v, 0.f);
                    C[(size_t)row*N + col] = v;
                }
            }
        }
}

// ---------------- pointwise kernels ----------------
__global__ void k_embed(const int* __restrict__ lin, const int* __restrict__ rin,
                        const float* __restrict__ emb)
{
    int row = blockIdx.x;
    int t = row >> 9, n = row & 511;
    int tok = t ? rin[n] : lin[n];
    float4 v = ((const float4*)(emb + (size_t)tok*1024))[threadIdx.x];
    ((uint2*)(g_Xh + (size_t)row*1024))[threadIdx.x] = f4_to_h4(v);
}

__global__ void k_soft(float* __restrict__ out)
{
    __shared__ float sh[512];
    int b = blockIdx.x;                 // t*16 + hop
    int t = b >> 4, hop = b & 15;
    int n = threadIdx.x;
    float v = g_LOG[(size_t)(t*512 + n)*16 + hop];
    sh[n] = v; __syncthreads();
    for (int s=256; s>0; s>>=1){ if (n < s) sh[n] = fmaxf(sh[n], sh[n+s]); __syncthreads(); }
    float mx = sh[0]; __syncthreads();
    float e = expf(v - mx);
    sh[n] = e; __syncthreads();
    for (int s=256; s>0; s>>=1){ if (n < s) sh[n] += sh[n+s]; __syncthreads(); }
    float a = e / sh[0];
    g_ALPHA[(size_t)b*512 + n] = a;
    out[5 + t*8192 + hop*512 + n] = a;
}

__global__ void k_lat(const float* __restrict__ w_lat, const float* __restrict__ b_lat)
{
    int m = blockIdx.x*256 + threadIdx.x;   // 1024
    float lv = b_lat[0], rv = b_lat[0];
    #pragma unroll
    for (int h=0; h<16; h++) {
        float w = w_lat[h];
        float sl = 0.f, sr = 0.f;
        #pragma unroll
        for (int z=0; z<4; z++) {
            sl += g_LSp[z*32768 + h*1024 + m];
            sr += g_LSp[z*32768 + (16 + h)*1024 + m];
        }
        lv += w * fmaxf(sl, 0.f);
        rv += w * fmaxf(sr, 0.f);
    }
    g_FR[m]        = fabsf(lv - rv);
    g_FR[1024 + m] = lv * rv;
    g_FR[2048 + m] = 0.5f * (lv + rv);
}

__global__ void k_fc(const float* __restrict__ w, const float* __restrict__ bb)
{
    int o = blockIdx.x*8 + (threadIdx.x >> 5);
    int lane = threadIdx.x & 31;
    const float* wr = w + (size_t)o*3072;
    float s = 0.f;
    for (int k=lane; k<3072; k+=32) s += g_FR[k]*wr[k];
    for (int d=16; d; d>>=1) s += __shfl_down_sync(0xffffffffu, s, d);
    if (!lane) { float v = s + bb[o]; g_FC[o] = v > 0.f ? v : 0.01f*v; }
}

__global__ void k_fc2out(const float* __restrict__ w_out, const float* __restrict__ b_out,
                         const float* __restrict__ w_out1, const float* __restrict__ b_out1,
                         float* __restrict__ out)
{
    __shared__ float fc2[256];
    __shared__ float logit[5];
    int tid = threadIdx.x;             // 256
    int wid = tid >> 5, lane = tid & 31;
    for (int it = 0; it < 4; it++) {
        int o = wid*32 + (it << 3) + (lane >> 2);
        float s = 0.f;
        for (int k = (lane & 3); k < 512; k += 4) s += g_FC[k]*w_out[(size_t)o*512 + k];
        s += __shfl_down_sync(0xffffffffu, s, 2);
        s += __shfl_down_sync(0xffffffffu, s, 1);
        if ((lane & 3) == 0) fc2[o] = sigm(s + b_out[o]);
    }
    __syncthreads();
    if (wid < 5) {
        float s = 0.f;
        for (int k = lane; k < 256; k += 32) s += fc2[k]*w_out1[wid*256 + k];
        for (int d = 16; d; d >>= 1) s += __shfl_down_sync(0xffffffffu, s, d);
        if (!lane) logit[wid] = s + b_out1[wid];
    }
    __syncthreads();
    if (tid == 0) {
        float mx = logit[0];
        for (int c=1;c<5;c++) mx = fmaxf(mx, logit[c]);
        float sum = 0.f;
        for (int c=0;c<5;c++) sum += expf(logit[c]-mx);
        float l = logf(sum);
        for (int c=0;c<5;c++) out[c] = logit[c] - mx - l;
    }
}

// ---------------- launch ----------------
extern "C" void kernel_launch(void* const* d_in, const int* in_sizes, int n_in,
                              void* d_out, int out_size)
{
    const int*   linputs    = (const int*)  d_in[0];
    const int*   rinputs    = (const int*)  d_in[1];
    const int*   child_idx  = (const int*)  d_in[2];
    const float* child_mask = (const float*)d_in[3];
    const float* emb        = (const float*)d_in[4];
    const float* w_ioux     = (const float*)d_in[5];
    const float* b_ioux     = (const float*)d_in[6];
    const float* w_iouh     = (const float*)d_in[7];
    const float* b_iouh     = (const float*)d_in[8];
    const float* w_fx       = (const float*)d_in[9];
    const float* b_fx       = (const float*)d_in[10];
    const float* w_fh       = (const float*)d_in[11];
    const float* b_fh       = (const float*)d_in[12];
    const float* ws1        = (const float*)d_in[13];
    const float* ws2        = (const float*)d_in[14];
    const float* wf         = (const float*)d_in[15];
    const float* w_lat      = (const float*)d_in[16];
    const float* b_lat      = (const float*)d_in[17];
    const float* w_fc       = (const float*)d_in[18];
    const float* b_fc       = (const float*)d_in[19];
    const float* w_out      = (const float*)d_in[20];
    const float* b_out      = (const float*)d_in[21];
    const float* w_out1     = (const float*)d_in[22];
    const float* b_out1     = (const float*)d_in[23];
    float* out = (float*)d_out;

    float *pH, *pHB, *pLOG, *pALPHA, *pM, *pLSp;
    cudaGetSymbolAddress((void**)&pH,     g_H);
    cudaGetSymbolAddress((void**)&pHB,    g_HB);
    cudaGetSymbolAddress((void**)&pLOG,   g_LOG);
    cudaGetSymbolAddress((void**)&pALPHA, g_ALPHA);
    cudaGetSymbolAddress((void**)&pM,     g_Mm);
    cudaGetSymbolAddress((void**)&pLSp,   g_LSp);

    // Size the persistent grid for guaranteed co-residency (deadlock-safe).
    static int nTreeBlk = 0;
    if (nTreeBlk == 0) {
        int perSM = 0, sms = 0, dev = 0;
        cudaGetDevice(&dev);
        cudaDeviceGetAttribute(&sms, cudaDevAttrMultiProcessorCount, dev);
        cudaOccupancyMaxActiveBlocksPerMultiprocessor(&perSM, k_tree, 256, 0);
        if (perSM < 1) perSM = 1;
        if (perSM > 2) perSM = 2;
        if (sms < 1) sms = 148;
        nTreeBlk = perSM * sms;
    }

    // 0) weight conversion to half
    k_cvtW<<<8448, 256>>>(w_ioux, w_fx, w_iouh, w_fh, ws1);

    // 1) embedding gather (half)
    k_embed<<<1024, 256>>>(linputs, rinputs, emb);

    // 2) fused input projections: M=1024, N=4096, K=1024
    gemm_h<0><<<dim3(64, 8, 1), 256>>>(b_ioux, b_fx);

    // 3) persistent kernel: leaves + all internal levels (grid barriers)
    k_tree<<<nTreeBlk, 256>>>(child_idx, child_mask, b_iouh, b_fh);

    // 4) attention
    gemm_h<2><<<dim3(4, 8, 1), 256>>>(nullptr, nullptr);
    gemm_s<true,0><<<dim3(1,16,1), 128>>>(pHB, ws2, nullptr, pLOG,
                                          1024, 16, 256, 256, 256, 0, 0, 0);
    k_soft<<<32, 512>>>(out);
    gemm_s<false,0><<<dim3(16,1,2), 128>>>(pALPHA, pH, nullptr, pM,
                                           16, 1024, 512, 512, 1024,
                                           16*512, 512*1024, 16*1024);

    // 5) head: wf GEMM split-K=4 (K slabs of 256), relu folded into k_lat
    gemm_s<false,0><<<dim3(16,1,4), 128>>>(pM, wf, nullptr, pLSp,
                                           32, 1024, 256, 1024, 1024,
                                           256, 256*1024, 32*1024);
    k_lat<<<4, 256>>>(w_lat, b_lat);
    k_fc<<<64, 256>>>(w_fc, b_fc);
    k_fc2out<<<1, 256>>>(w_out, b_out, w_out1, b_out1, out);
}